// round 1
// baseline (speedup 1.0000x reference)
#include <cuda_runtime.h>
#include <cstdint>

#define N_NODES 100000
#define N_HEDGES 40000
#define N_INC 600000
#define D 128

// Scratch accumulators (allocation-free: __device__ globals).
static __device__ float g_norm_v[(size_t)N_HEDGES * D];  // nodes -> edges accumulation
static __device__ float g_norm_e[(size_t)N_NODES * D];   // edges -> nodes accumulation

// ---------------------------------------------------------------------------
// Zero both scratch arrays. Grid sized exactly: (N_HEDGES+N_NODES)*D/4 float4s.
// ---------------------------------------------------------------------------
__global__ void zero_kernel() {
    size_t i = (size_t)blockIdx.x * blockDim.x + threadIdx.x;
    const size_t nv = (size_t)N_HEDGES * D / 4;
    const size_t ne = (size_t)N_NODES * D / 4;
    float4 z = make_float4(0.f, 0.f, 0.f, 0.f);
    if (i < nv) {
        reinterpret_cast<float4*>(g_norm_v)[i] = z;
    } else if (i < nv + ne) {
        reinterpret_cast<float4*>(g_norm_e)[i - nv] = z;
    }
}

// ---------------------------------------------------------------------------
// Weighted scatter-add: for each incidence i,
//   dst[dst_idx[i]] += (num_w[src_idx[i]] / den_w[dst_idx[i]]) * src_feat[src_idx[i]]
// One warp per incidence; each lane handles 4 of the 128 dims via a single
// red.global.add.v4.f32 (no-return reduction, 16B granularity).
// ---------------------------------------------------------------------------
__global__ void __launch_bounds__(256) scatter_kernel(
    const float* __restrict__ src_feat,   // [S, D]
    const float* __restrict__ num_w,      // [S, 1], indexed by src idx
    const float* __restrict__ den_w,      // [T, 1], indexed by dst idx
    const int*   __restrict__ src_idx,    // [N_INC]
    const int*   __restrict__ dst_idx,    // [N_INC]
    float*       __restrict__ dst)        // [T, D]
{
    int inc = (blockIdx.x * blockDim.x + threadIdx.x) >> 5;
    if (inc >= N_INC) return;
    int lane = threadIdx.x & 31;

    int s = __ldg(&src_idx[inc]);
    int t = __ldg(&dst_idx[inc]);
    float w = __ldg(&num_w[s]) / __ldg(&den_w[t]);

    float4 v = reinterpret_cast<const float4*>(src_feat + (size_t)s * D)[lane];
    float* p = dst + (size_t)t * D + lane * 4;
    asm volatile("red.global.add.v4.f32 [%0], {%1, %2, %3, %4};"
                 :: "l"(p), "f"(w * v.x), "f"(w * v.y), "f"(w * v.z), "f"(w * v.w)
                 : "memory");
}

// ---------------------------------------------------------------------------
// GEMM: Out[m][n] (op)= A[m][:] . W[n][:] + bias[n]     (N = K = 128)
// Block: 256 threads, tile 64 rows x 128 cols.
// Smem: Ws transposed [128][132] (pad 132 -> float4-aligned, conflict-free
//       lane-consecutive reads), As [64][128].
// Thread micro-tile: 8 rows x 4 cols (warp = 8 rows, lane*4 = col offset).
// RELU:   apply relu(acc+bias)
// ACCUM:  Out += (acc + bias)   (used for the efeat @ W_ef^T + b_ef add)
// ---------------------------------------------------------------------------
template <bool RELU, bool ACCUM>
__global__ void __launch_bounds__(256) gemm128_kernel(
    const float* __restrict__ A, int M,
    const float* __restrict__ W,     // [128,128] row-major, Out = A @ W^T
    const float* __restrict__ bias,  // [128]
    float*       __restrict__ Out)   // [M,128]
{
    extern __shared__ float smem[];
    float* Ws = smem;                 // 128*132 floats
    float* As = smem + 128 * 132;     // 64*128 floats

    int tid = threadIdx.x;

    // Load W transposed: Ws[k][n] = W[n][k]
    for (int i = tid; i < 128 * 128; i += 256) {
        int n = i >> 7;
        int k = i & 127;
        Ws[k * 132 + n] = W[i];
    }

    // Load A tile (64 rows), zero-pad out-of-range rows.
    int m_base = blockIdx.x * 64;
    for (int i = tid; i < 64 * 32; i += 256) {
        int r = i >> 5;
        int c = i & 31;
        int m = m_base + r;
        float4 v = (m < M) ? reinterpret_cast<const float4*>(A)[(size_t)m * 32 + c]
                           : make_float4(0.f, 0.f, 0.f, 0.f);
        reinterpret_cast<float4*>(As)[i] = v;
    }
    __syncthreads();

    int lane = tid & 31;
    int wrp  = tid >> 5;
    int n0 = lane * 4;
    int m0 = wrp * 8;

    float acc[8][4];
    #pragma unroll
    for (int r = 0; r < 8; r++)
        #pragma unroll
        for (int c = 0; c < 4; c++)
            acc[r][c] = 0.f;

    #pragma unroll 4
    for (int k = 0; k < 128; k++) {
        float4 w = *reinterpret_cast<const float4*>(&Ws[k * 132 + n0]);
        #pragma unroll
        for (int r = 0; r < 8; r++) {
            float a = As[(m0 + r) * 128 + k];
            acc[r][0] += a * w.x;
            acc[r][1] += a * w.y;
            acc[r][2] += a * w.z;
            acc[r][3] += a * w.w;
        }
    }

    float4 b = *reinterpret_cast<const float4*>(&bias[n0]);
    #pragma unroll
    for (int r = 0; r < 8; r++) {
        int m = m_base + m0 + r;
        if (m < M) {
            float4 o;
            o.x = acc[r][0] + b.x;
            o.y = acc[r][1] + b.y;
            o.z = acc[r][2] + b.z;
            o.w = acc[r][3] + b.w;
            if (RELU) {
                o.x = fmaxf(o.x, 0.f);
                o.y = fmaxf(o.y, 0.f);
                o.z = fmaxf(o.z, 0.f);
                o.w = fmaxf(o.w, 0.f);
            }
            float4* po = reinterpret_cast<float4*>(Out + (size_t)m * 128 + n0);
            if (ACCUM) {
                float4 prev = *po;
                o.x += prev.x;
                o.y += prev.y;
                o.z += prev.z;
                o.w += prev.w;
            }
            *po = o;
        }
    }
}

extern "C" void kernel_launch(void* const* d_in, const int* in_sizes, int n_in,
                              void* d_out, int out_size) {
    (void)in_sizes; (void)n_in; (void)out_size;

    const float* vfeat = (const float*)d_in[0];
    const float* efeat = (const float*)d_in[1];
    const float* v_reg_weight = (const float*)d_in[2];
    const float* v_reg_sum    = (const float*)d_in[3];
    const float* e_reg_weight = (const float*)d_in[4];
    const float* e_reg_sum    = (const float*)d_in[5];
    const float* W_ve = (const float*)d_in[6];
    const float* b_ve = (const float*)d_in[7];
    const float* W_ev = (const float*)d_in[8];
    const float* b_ev = (const float*)d_in[9];
    const float* W_ef = (const float*)d_in[10];
    const float* b_ef = (const float*)d_in[11];
    const int* node_idx = (const int*)d_in[12];
    const int* edge_idx = (const int*)d_in[13];

    float* out = (float*)d_out;
    float* vfeat_out = out;                            // [N_NODES, D]
    float* efeat_out = out + (size_t)N_NODES * D;      // [N_HEDGES, D]

    float* norm_v_ptr = nullptr;
    float* norm_e_ptr = nullptr;
    cudaGetSymbolAddress((void**)&norm_v_ptr, g_norm_v);
    cudaGetSymbolAddress((void**)&norm_e_ptr, g_norm_e);

    const int smem_bytes = (128 * 132 + 64 * 128) * (int)sizeof(float);  // 100352
    cudaFuncSetAttribute(gemm128_kernel<true, false>,
                         cudaFuncAttributeMaxDynamicSharedMemorySize, smem_bytes);
    cudaFuncSetAttribute(gemm128_kernel<false, true>,
                         cudaFuncAttributeMaxDynamicSharedMemorySize, smem_bytes);

    // 1. zero scratch
    zero_kernel<<<17500, 256>>>();

    // 2. scatter nodes -> edges:  g_norm_v[e] += (v_reg_weight[n]/e_reg_sum[e]) * vfeat[n]
    scatter_kernel<<<(N_INC * 32 + 255) / 256, 256>>>(
        vfeat, v_reg_weight, e_reg_sum, node_idx, edge_idx, norm_v_ptr);

    // 3. efeat_out = relu(g_norm_v @ W_ve^T + b_ve)
    gemm128_kernel<true, false><<<N_HEDGES / 64, 256, smem_bytes>>>(
        norm_v_ptr, N_HEDGES, W_ve, b_ve, efeat_out);

    // 4. efeat_out += efeat @ W_ef^T + b_ef
    gemm128_kernel<false, true><<<N_HEDGES / 64, 256, smem_bytes>>>(
        efeat, N_HEDGES, W_ef, b_ef, efeat_out);

    // 5. scatter edges -> nodes:  g_norm_e[v] += (e_reg_weight[e]/v_reg_sum[v]) * efeat_out[e]
    scatter_kernel<<<(N_INC * 32 + 255) / 256, 256>>>(
        efeat_out, e_reg_weight, v_reg_sum, edge_idx, node_idx, norm_e_ptr);

    // 6. vfeat_out = relu(g_norm_e @ W_ev^T + b_ev)
    gemm128_kernel<true, false><<<(N_NODES + 63) / 64, 256, smem_bytes>>>(
        norm_e_ptr, N_NODES, W_ev, b_ev, vfeat_out);
}

// round 2
// speedup vs baseline: 1.0594x; 1.0594x over previous
#include <cuda_runtime.h>
#include <cstdint>

#define N_NODES 100000
#define N_HEDGES 40000
#define N_INC 600000
#define D 128

// ---------------------------------------------------------------------------
// Scratch (allocation-free: __device__ globals).
// ---------------------------------------------------------------------------
static __device__ float g_norm_v[(size_t)N_HEDGES * D];  // nodes -> edges accumulation
static __device__ float g_norm_e[(size_t)N_NODES * D];   // edges -> nodes accumulation
static __device__ uint32_t g_Whi[3][D * D];              // tf32 hi parts of W_ve, W_ef, W_ev
static __device__ uint32_t g_Wlo[3][D * D];              // tf32 lo parts

__device__ __forceinline__ uint32_t f32_to_tf32(float x) {
    uint32_t r;
    asm("cvt.rna.tf32.f32 %0, %1;" : "=r"(r) : "f"(x));
    return r;
}

// ---------------------------------------------------------------------------
// Zero both scratch accumulators.
// ---------------------------------------------------------------------------
__global__ void zero_kernel() {
    size_t i = (size_t)blockIdx.x * blockDim.x + threadIdx.x;
    const size_t nv = (size_t)N_HEDGES * D / 4;
    const size_t ne = (size_t)N_NODES * D / 4;
    float4 z = make_float4(0.f, 0.f, 0.f, 0.f);
    if (i < nv) {
        reinterpret_cast<float4*>(g_norm_v)[i] = z;
    } else if (i < nv + ne) {
        reinterpret_cast<float4*>(g_norm_e)[i - nv] = z;
    }
}

// ---------------------------------------------------------------------------
// Split the three 128x128 weight matrices into tf32 hi/lo pairs.
// x = hi + lo (exactly, up to tf32(lo) rounding ~2^-22 relative).
// ---------------------------------------------------------------------------
__global__ void wsplit_kernel(const float* __restrict__ W0,
                              const float* __restrict__ W1,
                              const float* __restrict__ W2) {
    int i = blockIdx.x * blockDim.x + threadIdx.x;  // 3 * 16384 threads
    if (i >= 3 * D * D) return;
    int w = i >> 14;
    int j = i & (D * D - 1);
    const float* W = (w == 0) ? W0 : (w == 1) ? W1 : W2;
    float x = W[j];
    uint32_t hi = f32_to_tf32(x);
    float lo = x - __uint_as_float(hi);
    g_Whi[w][j] = hi;
    g_Wlo[w][j] = f32_to_tf32(lo);
}

// ---------------------------------------------------------------------------
// Weighted scatter-add via red.global.add.v4.f32 (warp per incidence).
// ---------------------------------------------------------------------------
__global__ void __launch_bounds__(256) scatter_kernel(
    const float* __restrict__ src_feat,
    const float* __restrict__ num_w,
    const float* __restrict__ den_w,
    const int*   __restrict__ src_idx,
    const int*   __restrict__ dst_idx,
    float*       __restrict__ dst)
{
    int inc = (blockIdx.x * blockDim.x + threadIdx.x) >> 5;
    if (inc >= N_INC) return;
    int lane = threadIdx.x & 31;

    int s = __ldg(&src_idx[inc]);
    int t = __ldg(&dst_idx[inc]);
    float w = __ldg(&num_w[s]) / __ldg(&den_w[t]);

    float4 v = reinterpret_cast<const float4*>(src_feat + (size_t)s * D)[lane];
    float* p = dst + (size_t)t * D + lane * 4;
    asm volatile("red.global.add.v4.f32 [%0], {%1, %2, %3, %4};"
                 :: "l"(p), "f"(w * v.x), "f"(w * v.y), "f"(w * v.z), "f"(w * v.w)
                 : "memory");
}

// ---------------------------------------------------------------------------
// Tensor-core GEMM (tf32 x3 split, fp32 accumulate), Out = A @ W^T (+ bias).
//
// Block: 256 threads, tile 128(M) x 128(N). Warp grid 4(M) x 2(N):
//   each warp owns 32 rows (2 m16 fragments) x 64 cols (8 n8 tiles).
// Smem: Whi[n][k] pad 132, Wlo[n][k] pad 132 (tf32 bits), As[m][k] pad 132 (f32).
//   Fragment loads are bank-conflict-free: bank index == lane for both A and B.
// 3xTF32: C += Ahi*Bhi + Alo*Bhi + Ahi*Blo  (error ~1e-6 rel).
//
// FUSED: two phases sharing accumulators:
//   phase 0: C = A0 @ W[w0]^T ; C = relu(C + bias0)
//   phase 1: C += A1 @ W[w1]^T ; C += bias1 ; store
// !FUSED:  C = A0 @ W[w0]^T ; C = relu(C + bias0) ; store
// ---------------------------------------------------------------------------
#define MMA_TF32(C, A, b0, b1)                                                 \
    asm volatile("mma.sync.aligned.m16n8k8.row.col.f32.tf32.tf32.f32 "         \
                 "{%0,%1,%2,%3}, {%4,%5,%6,%7}, {%8,%9}, {%0,%1,%2,%3};"       \
                 : "+f"(C[0]), "+f"(C[1]), "+f"(C[2]), "+f"(C[3])              \
                 : "r"(A[0]), "r"(A[1]), "r"(A[2]), "r"(A[3]),                 \
                   "r"(b0), "r"(b1))

template <bool FUSED>
__global__ void __launch_bounds__(256) gemm_tc_kernel(
    const float* __restrict__ A0, const float* __restrict__ bias0, int w0,
    const float* __restrict__ A1, const float* __restrict__ bias1, int w1,
    int M, float* __restrict__ Out)
{
    extern __shared__ float smem[];
    uint32_t* Whi_s = reinterpret_cast<uint32_t*>(smem);       // 128*132
    uint32_t* Wlo_s = Whi_s + 128 * 132;                       // 128*132
    float*    As    = smem + 2 * 128 * 132;                    // 128*132

    const int tid  = threadIdx.x;
    const int lane = tid & 31;
    const int warp = tid >> 5;
    const int wm   = warp & 3;   // M quadrant: rows wm*32 .. wm*32+31
    const int wn   = warp >> 2;  // N half:    cols wn*64 .. wn*64+63
    const int lr   = lane >> 2;  // 0..7
    const int lq   = lane & 3;   // 0..3
    const int m_base = blockIdx.x * 128;

    float c[2][8][4];
    #pragma unroll
    for (int mf = 0; mf < 2; mf++)
        #pragma unroll
        for (int nt = 0; nt < 8; nt++)
            #pragma unroll
            for (int i = 0; i < 4; i++)
                c[mf][nt][i] = 0.f;

    const int n_phases = FUSED ? 2 : 1;
    for (int phase = 0; phase < n_phases; phase++) {
        const float* A = phase ? A1 : A0;
        const uint32_t* __restrict__ Wh = g_Whi[phase ? w1 : w0];
        const uint32_t* __restrict__ Wl = g_Wlo[phase ? w1 : w0];

        if (phase) __syncthreads();  // previous-phase smem reads complete

        // Stage W hi/lo: Whi_s[n*132+k] = Wh[n*128+k]
        for (int i = tid; i < D * D; i += 256) {
            int n = i >> 7;
            int k = i & 127;
            Whi_s[n * 132 + k] = Wh[i];
            Wlo_s[n * 132 + k] = Wl[i];
        }
        // Stage A tile (128 rows), zero-pad rows >= M.
        for (int i = tid; i < 128 * 32; i += 256) {
            int m = i >> 5;
            int cc = i & 31;
            int gm = m_base + m;
            float4 v = (gm < M)
                ? reinterpret_cast<const float4*>(A)[(size_t)gm * 32 + cc]
                : make_float4(0.f, 0.f, 0.f, 0.f);
            *reinterpret_cast<float4*>(&As[m * 132 + cc * 4]) = v;
        }
        __syncthreads();

        #pragma unroll 2
        for (int kt = 0; kt < 16; kt++) {
            const int k0 = kt * 8;

            uint32_t ahi[2][4], alo[2][4];
            #pragma unroll
            for (int mf = 0; mf < 2; mf++) {
                int mrow = wm * 32 + mf * 16 + lr;
                float a0 = As[mrow * 132 + k0 + lq];
                float a1 = As[(mrow + 8) * 132 + k0 + lq];
                float a2 = As[mrow * 132 + k0 + lq + 4];
                float a3 = As[(mrow + 8) * 132 + k0 + lq + 4];
                ahi[mf][0] = f32_to_tf32(a0);
                ahi[mf][1] = f32_to_tf32(a1);
                ahi[mf][2] = f32_to_tf32(a2);
                ahi[mf][3] = f32_to_tf32(a3);
                alo[mf][0] = f32_to_tf32(a0 - __uint_as_float(ahi[mf][0]));
                alo[mf][1] = f32_to_tf32(a1 - __uint_as_float(ahi[mf][1]));
                alo[mf][2] = f32_to_tf32(a2 - __uint_as_float(ahi[mf][2]));
                alo[mf][3] = f32_to_tf32(a3 - __uint_as_float(ahi[mf][3]));
            }

            #pragma unroll
            for (int nt = 0; nt < 8; nt++) {
                int nrow = wn * 64 + nt * 8 + lr;
                uint32_t bh0 = Whi_s[nrow * 132 + k0 + lq];
                uint32_t bh1 = Whi_s[nrow * 132 + k0 + lq + 4];
                uint32_t bl0 = Wlo_s[nrow * 132 + k0 + lq];
                uint32_t bl1 = Wlo_s[nrow * 132 + k0 + lq + 4];
                #pragma unroll
                for (int mf = 0; mf < 2; mf++) {
                    MMA_TF32(c[mf][nt], ahi[mf], bh0, bh1);
                    MMA_TF32(c[mf][nt], alo[mf], bh0, bh1);
                    MMA_TF32(c[mf][nt], ahi[mf], bl0, bl1);
                }
            }
        }

        // Mid-fusion epilogue: relu(C + bias0) after phase 0 of the fused path.
        if (FUSED && phase == 0) {
            #pragma unroll
            for (int nt = 0; nt < 8; nt++) {
                float2 b = *reinterpret_cast<const float2*>(
                    &bias0[wn * 64 + nt * 8 + 2 * lq]);
                #pragma unroll
                for (int mf = 0; mf < 2; mf++) {
                    c[mf][nt][0] = fmaxf(c[mf][nt][0] + b.x, 0.f);
                    c[mf][nt][1] = fmaxf(c[mf][nt][1] + b.y, 0.f);
                    c[mf][nt][2] = fmaxf(c[mf][nt][2] + b.x, 0.f);
                    c[mf][nt][3] = fmaxf(c[mf][nt][3] + b.y, 0.f);
                }
            }
        }
    }

    // Final epilogue: add bias, relu if !FUSED, store.
    const float* bias_f = FUSED ? bias1 : bias0;
    #pragma unroll
    for (int nt = 0; nt < 8; nt++) {
        int col = wn * 64 + nt * 8 + 2 * lq;
        float2 b = *reinterpret_cast<const float2*>(&bias_f[col]);
        #pragma unroll
        for (int mf = 0; mf < 2; mf++) {
            int row0 = m_base + wm * 32 + mf * 16 + lr;
            float2 o01, o23;
            o01.x = c[mf][nt][0] + b.x;
            o01.y = c[mf][nt][1] + b.y;
            o23.x = c[mf][nt][2] + b.x;
            o23.y = c[mf][nt][3] + b.y;
            if (!FUSED) {
                o01.x = fmaxf(o01.x, 0.f);
                o01.y = fmaxf(o01.y, 0.f);
                o23.x = fmaxf(o23.x, 0.f);
                o23.y = fmaxf(o23.y, 0.f);
            }
            if (row0 < M)
                *reinterpret_cast<float2*>(&Out[(size_t)row0 * D + col]) = o01;
            if (row0 + 8 < M)
                *reinterpret_cast<float2*>(&Out[(size_t)(row0 + 8) * D + col]) = o23;
        }
    }
}

extern "C" void kernel_launch(void* const* d_in, const int* in_sizes, int n_in,
                              void* d_out, int out_size) {
    (void)in_sizes; (void)n_in; (void)out_size;

    const float* vfeat = (const float*)d_in[0];
    const float* efeat = (const float*)d_in[1];
    const float* v_reg_weight = (const float*)d_in[2];
    const float* v_reg_sum    = (const float*)d_in[3];
    const float* e_reg_weight = (const float*)d_in[4];
    const float* e_reg_sum    = (const float*)d_in[5];
    const float* W_ve = (const float*)d_in[6];
    const float* b_ve = (const float*)d_in[7];
    const float* W_ev = (const float*)d_in[8];
    const float* b_ev = (const float*)d_in[9];
    const float* W_ef = (const float*)d_in[10];
    const float* b_ef = (const float*)d_in[11];
    const int* node_idx = (const int*)d_in[12];
    const int* edge_idx = (const int*)d_in[13];

    float* out = (float*)d_out;
    float* vfeat_out = out;                            // [N_NODES, D]
    float* efeat_out = out + (size_t)N_NODES * D;      // [N_HEDGES, D]

    float* norm_v_ptr = nullptr;
    float* norm_e_ptr = nullptr;
    cudaGetSymbolAddress((void**)&norm_v_ptr, g_norm_v);
    cudaGetSymbolAddress((void**)&norm_e_ptr, g_norm_e);

    const int smem_bytes = 3 * 128 * 132 * (int)sizeof(float);  // 202752
    cudaFuncSetAttribute(gemm_tc_kernel<true>,
                         cudaFuncAttributeMaxDynamicSharedMemorySize, smem_bytes);
    cudaFuncSetAttribute(gemm_tc_kernel<false>,
                         cudaFuncAttributeMaxDynamicSharedMemorySize, smem_bytes);

    // 1. zero scratch
    zero_kernel<<<17500, 256>>>();

    // 2. split W_ve(0), W_ef(1), W_ev(2) into tf32 hi/lo
    wsplit_kernel<<<(3 * D * D + 255) / 256, 256>>>(W_ve, W_ef, W_ev);

    // 3. scatter nodes -> edges
    scatter_kernel<<<(N_INC * 32 + 255) / 256, 256>>>(
        vfeat, v_reg_weight, e_reg_sum, node_idx, edge_idx, norm_v_ptr);

    // 4. efeat_out = relu(norm_v @ W_ve^T + b_ve) + efeat @ W_ef^T + b_ef  (fused)
    gemm_tc_kernel<true><<<(N_HEDGES + 127) / 128, 256, smem_bytes>>>(
        norm_v_ptr, b_ve, 0, efeat, b_ef, 1, N_HEDGES, efeat_out);

    // 5. scatter edges -> nodes
    scatter_kernel<<<(N_INC * 32 + 255) / 256, 256>>>(
        efeat_out, e_reg_weight, v_reg_sum, edge_idx, node_idx, norm_e_ptr);

    // 6. vfeat_out = relu(norm_e @ W_ev^T + b_ev)
    gemm_tc_kernel<false><<<(N_NODES + 127) / 128, 256, smem_bytes>>>(
        norm_e_ptr, b_ev, 2, nullptr, nullptr, 0, N_NODES, vfeat_out);
}

// round 4
// speedup vs baseline: 1.4792x; 1.3963x over previous
#include <cuda_runtime.h>
#include <cuda_bf16.h>
#include <cstdint>

#define N_NODES 100000
#define N_HEDGES 40000
#define N_INC 600000
#define D 128

// smem tile row pitch: 128 bf16 = 256B data + 16B pad = 272B.
// 272 mod 128 == 16  ->  ldmatrix 8-row address sets hit distinct 16B groups.
#define PITCH_B 272
#define W_ROW_U16 136   // global pre-split W row pitch in bf16 elems

// ---------------------------------------------------------------------------
// Scratch (allocation-free __device__ globals).
// ---------------------------------------------------------------------------
static __device__ float g_norm_v[(size_t)N_HEDGES * D];
static __device__ float g_norm_e[(size_t)N_NODES * D];
// W pre-split to bf16 hi/lo in the exact smem layout ([128][136] bf16 rows).
static __device__ __nv_bfloat16 g_Wh[3][D * W_ROW_U16];
static __device__ __nv_bfloat16 g_Wl[3][D * W_ROW_U16];

// ---------------------------------------------------------------------------
__global__ void zero_kernel() {
    size_t i = (size_t)blockIdx.x * blockDim.x + threadIdx.x;
    const size_t nv = (size_t)N_HEDGES * D / 4;
    const size_t ne = (size_t)N_NODES * D / 4;
    float4 z = make_float4(0.f, 0.f, 0.f, 0.f);
    if (i < nv) reinterpret_cast<float4*>(g_norm_v)[i] = z;
    else if (i < nv + ne) reinterpret_cast<float4*>(g_norm_e)[i - nv] = z;
}

__global__ void wsplit_kernel(const float* __restrict__ W0,
                              const float* __restrict__ W1,
                              const float* __restrict__ W2) {
    int i = blockIdx.x * blockDim.x + threadIdx.x;
    if (i >= 3 * D * D) return;
    int w = i >> 14;
    int j = i & (D * D - 1);
    const float* W = (w == 0) ? W0 : (w == 1) ? W1 : W2;
    int n = j >> 7, k = j & 127;
    float x = W[j];
    __nv_bfloat16 hi = __float2bfloat16(x);
    __nv_bfloat16 lo = __float2bfloat16(x - __bfloat162float(hi));
    g_Wh[w][n * W_ROW_U16 + k] = hi;
    g_Wl[w][n * W_ROW_U16 + k] = lo;
}

// ---------------------------------------------------------------------------
// Weighted scatter-add via red.global.add.v4.f32 (warp per incidence).
// ---------------------------------------------------------------------------
__global__ void __launch_bounds__(256) scatter_kernel(
    const float* __restrict__ src_feat, const float* __restrict__ num_w,
    const float* __restrict__ den_w, const int* __restrict__ src_idx,
    const int* __restrict__ dst_idx, float* __restrict__ dst)
{
    int inc = (blockIdx.x * blockDim.x + threadIdx.x) >> 5;
    if (inc >= N_INC) return;
    int lane = threadIdx.x & 31;
    int s = __ldg(&src_idx[inc]);
    int t = __ldg(&dst_idx[inc]);
    float w = __ldg(&num_w[s]) / __ldg(&den_w[t]);
    float4 v = reinterpret_cast<const float4*>(src_feat + (size_t)s * D)[lane];
    float* p = dst + (size_t)t * D + lane * 4;
    asm volatile("red.global.add.v4.f32 [%0], {%1, %2, %3, %4};"
                 :: "l"(p), "f"(w * v.x), "f"(w * v.y), "f"(w * v.z), "f"(w * v.w)
                 : "memory");
}

// ---------------------------------------------------------------------------
// PTX helpers
// ---------------------------------------------------------------------------
__device__ __forceinline__ uint32_t smem_u32(const void* p) {
    uint32_t a;
    asm("{ .reg .u64 t; cvta.to.shared.u64 t, %1; cvt.u32.u64 %0, t; }"
        : "=r"(a) : "l"(p));
    return a;
}
__device__ __forceinline__ void ldm_x4(uint32_t* r, uint32_t addr) {
    asm volatile("ldmatrix.sync.aligned.m8n8.x4.shared.b16 {%0,%1,%2,%3}, [%4];"
                 : "=r"(r[0]), "=r"(r[1]), "=r"(r[2]), "=r"(r[3]) : "r"(addr));
}
__device__ __forceinline__ void mma_bf16(float* c, const uint32_t* a,
                                         uint32_t b0, uint32_t b1) {
    asm volatile("mma.sync.aligned.m16n8k16.row.col.f32.bf16.bf16.f32 "
                 "{%0,%1,%2,%3},{%4,%5,%6,%7},{%8,%9},{%0,%1,%2,%3};"
                 : "+f"(c[0]), "+f"(c[1]), "+f"(c[2]), "+f"(c[3])
                 : "r"(a[0]), "r"(a[1]), "r"(a[2]), "r"(a[3]), "r"(b0), "r"(b1));
}
__device__ __forceinline__ uint32_t pack_bf16x2(float x, float y) {
    __nv_bfloat16 hx = __float2bfloat16(x), hy = __float2bfloat16(y);
    return (uint32_t)__bfloat16_as_ushort(hx) | ((uint32_t)__bfloat16_as_ushort(hy) << 16);
}

// smem byte offsets
#define SM_AHI 0
#define SM_ALO (SM_AHI + 64 * PITCH_B)        // 17408
#define SM_WHI (SM_ALO + 64 * PITCH_B)        // 34816
#define SM_WLO (SM_WHI + 128 * PITCH_B)       // 69632
#define SM_TOTAL (SM_WLO + 128 * PITCH_B)     // 104448

// ---------------------------------------------------------------------------
// bf16x3 mma.sync GEMM: Out = A @ W^T (+bias, relu). 64(M)x128(N) tile/CTA.
// FUSED: phase0 C=A0@W0^T, relu(C+bias0); phase1 C+=A1@W1^T; C+=bias1; store.
// !FUSED: C=A0@W0^T; relu(C+bias0); store.
// Warp grid: 2(M, 32 rows each) x 4(N, 32 cols each). Frags: 2 m16 x 4 n8.
// ---------------------------------------------------------------------------
template <bool FUSED>
__global__ void __launch_bounds__(256) gemm_bf16_kernel(
    const float* __restrict__ A0, const float* __restrict__ bias0,
    const __nv_bfloat16* __restrict__ Wh0, const __nv_bfloat16* __restrict__ Wl0,
    const float* __restrict__ A1, const float* __restrict__ bias1,
    const __nv_bfloat16* __restrict__ Wh1, const __nv_bfloat16* __restrict__ Wl1,
    int M, float* __restrict__ Out)
{
    extern __shared__ char smem[];
    const uint32_t sb = smem_u32(smem);
    const int tid = threadIdx.x;
    const int lane = tid & 31;
    const int warp = tid >> 5;
    const int wm = warp & 1;       // M half: rows wm*32..+31
    const int wn = warp >> 1;      // N quarter: cols wn*32..+31
    const int m_base = blockIdx.x * 64;

    float c[2][4][4];
    #pragma unroll
    for (int mf = 0; mf < 2; mf++)
        #pragma unroll
        for (int nt = 0; nt < 4; nt++)
            #pragma unroll
            for (int i = 0; i < 4; i++) c[mf][nt][i] = 0.f;

    // ldmatrix per-lane address offsets
    const int rA = (lane & 7) + ((lane >> 3) & 1) * 8;   // A row within m16
    const int kA = ((lane >> 4) & 1) * 8;                // A k-half
    const int rB = (lane & 7) + ((lane >> 4) & 1) * 8;   // B n within n16 pair
    const int kB = ((lane >> 3) & 1) * 8;                // B k-half
    const uint32_t aoff = (uint32_t)((wm * 32 + rA) * PITCH_B + kA * 2);
    const uint32_t boff = (uint32_t)((wn * 32 + rB) * PITCH_B + kB * 2);

    const int n_phases = FUSED ? 2 : 1;
    for (int phase = 0; phase < n_phases; phase++) {
        const float* A = phase ? A1 : A0;
        const uint4* wh4 = reinterpret_cast<const uint4*>(phase ? Wh1 : Wh0);
        const uint4* wl4 = reinterpret_cast<const uint4*>(phase ? Wl1 : Wl0);

        if (phase) __syncthreads();

        // Stage W hi/lo: raw linear copy, layouts identical (128 x 272B).
        {
            uint4* dh = reinterpret_cast<uint4*>(smem + SM_WHI);
            uint4* dl = reinterpret_cast<uint4*>(smem + SM_WLO);
            #pragma unroll
            for (int i = tid; i < 128 * PITCH_B / 16; i += 256) {
                dh[i] = wh4[i];
                dl[i] = wl4[i];
            }
        }
        // Stage A: one (row, 32-col seg) per thread; f32 -> bf16 hi/lo.
        {
            int row = tid >> 2;
            int seg = tid & 3;
            int gm = m_base + row;
            float v[32];
            if (gm < M) {
                const float4* ap = reinterpret_cast<const float4*>(A)
                                   + (size_t)gm * 32 + seg * 8;
                #pragma unroll
                for (int q = 0; q < 8; q++) {
                    float4 f = ap[q];
                    v[4 * q] = f.x; v[4 * q + 1] = f.y;
                    v[4 * q + 2] = f.z; v[4 * q + 3] = f.w;
                }
            } else {
                #pragma unroll
                for (int q = 0; q < 32; q++) v[q] = 0.f;
            }
            uint32_t hp[16], lp[16];
            #pragma unroll
            for (int q = 0; q < 16; q++) {
                float x = v[2 * q], y = v[2 * q + 1];
                uint32_t h = pack_bf16x2(x, y);
                float hx = __bfloat162float(__ushort_as_bfloat16((unsigned short)(h & 0xFFFF)));
                float hy = __bfloat162float(__ushort_as_bfloat16((unsigned short)(h >> 16)));
                hp[q] = h;
                lp[q] = pack_bf16x2(x - hx, y - hy);
            }
            char* dst_h = smem + SM_AHI + row * PITCH_B + seg * 64;
            char* dst_l = smem + SM_ALO + row * PITCH_B + seg * 64;
            #pragma unroll
            for (int q = 0; q < 4; q++) {
                *reinterpret_cast<uint4*>(dst_h + 16 * q) =
                    make_uint4(hp[4 * q], hp[4 * q + 1], hp[4 * q + 2], hp[4 * q + 3]);
                *reinterpret_cast<uint4*>(dst_l + 16 * q) =
                    make_uint4(lp[4 * q], lp[4 * q + 1], lp[4 * q + 2], lp[4 * q + 3]);
            }
        }
        __syncthreads();

        // Mainloop: 8 k-steps of k16.
        #pragma unroll
        for (int kt = 0; kt < 8; kt++) {
            const uint32_t kb = kt * 32;  // 16 bf16 = 32 bytes
            uint32_t ah[2][4], al[2][4];
            ldm_x4(ah[0], sb + SM_AHI + aoff + kb);
            ldm_x4(ah[1], sb + SM_AHI + aoff + 16 * PITCH_B + kb);
            ldm_x4(al[0], sb + SM_ALO + aoff + kb);
            ldm_x4(al[1], sb + SM_ALO + aoff + 16 * PITCH_B + kb);
            // B pairs: x4 loads two n8 tiles (r0,r1 = tile p*2; r2,r3 = tile p*2+1)
            uint32_t bh[8], bl[8];
            ldm_x4(&bh[0], sb + SM_WHI + boff + kb);
            ldm_x4(&bh[4], sb + SM_WHI + boff + 16 * PITCH_B + kb);
            ldm_x4(&bl[0], sb + SM_WLO + boff + kb);
            ldm_x4(&bl[4], sb + SM_WLO + boff + 16 * PITCH_B + kb);

            #pragma unroll
            for (int nt = 0; nt < 4; nt++) {
                uint32_t b0h = bh[2 * nt], b1h = bh[2 * nt + 1];
                uint32_t b0l = bl[2 * nt], b1l = bl[2 * nt + 1];
                #pragma unroll
                for (int mf = 0; mf < 2; mf++) {
                    mma_bf16(c[mf][nt], ah[mf], b0h, b1h);
                    mma_bf16(c[mf][nt], al[mf], b0h, b1h);
                    mma_bf16(c[mf][nt], ah[mf], b0l, b1l);
                }
            }
        }

        if (FUSED && phase == 0) {
            #pragma unroll
            for (int nt = 0; nt < 4; nt++) {
                int col = wn * 32 + nt * 8 + 2 * (lane & 3);
                float2 b = __ldg(reinterpret_cast<const float2*>(&bias0[col]));
                #pragma unroll
                for (int mf = 0; mf < 2; mf++) {
                    c[mf][nt][0] = fmaxf(c[mf][nt][0] + b.x, 0.f);
                    c[mf][nt][1] = fmaxf(c[mf][nt][1] + b.y, 0.f);
                    c[mf][nt][2] = fmaxf(c[mf][nt][2] + b.x, 0.f);
                    c[mf][nt][3] = fmaxf(c[mf][nt][3] + b.y, 0.f);
                }
            }
        }
    }

    // Final epilogue
    const float* bias_f = FUSED ? bias1 : bias0;
    #pragma unroll
    for (int nt = 0; nt < 4; nt++) {
        int col = wn * 32 + nt * 8 + 2 * (lane & 3);
        float2 b = __ldg(reinterpret_cast<const float2*>(&bias_f[col]));
        #pragma unroll
        for (int mf = 0; mf < 2; mf++) {
            int row0 = m_base + wm * 32 + mf * 16 + (lane >> 2);
            float2 o01 = make_float2(c[mf][nt][0] + b.x, c[mf][nt][1] + b.y);
            float2 o23 = make_float2(c[mf][nt][2] + b.x, c[mf][nt][3] + b.y);
            if (!FUSED) {
                o01.x = fmaxf(o01.x, 0.f); o01.y = fmaxf(o01.y, 0.f);
                o23.x = fmaxf(o23.x, 0.f); o23.y = fmaxf(o23.y, 0.f);
            }
            if (row0 < M)
                *reinterpret_cast<float2*>(&Out[(size_t)row0 * D + col]) = o01;
            if (row0 + 8 < M)
                *reinterpret_cast<float2*>(&Out[(size_t)(row0 + 8) * D + col]) = o23;
        }
    }
}

extern "C" void kernel_launch(void* const* d_in, const int* in_sizes, int n_in,
                              void* d_out, int out_size) {
    (void)in_sizes; (void)n_in; (void)out_size;

    const float* vfeat = (const float*)d_in[0];
    const float* efeat = (const float*)d_in[1];
    const float* v_reg_weight = (const float*)d_in[2];
    const float* v_reg_sum    = (const float*)d_in[3];
    const float* e_reg_weight = (const float*)d_in[4];
    const float* e_reg_sum    = (const float*)d_in[5];
    const float* W_ve = (const float*)d_in[6];
    const float* b_ve = (const float*)d_in[7];
    const float* W_ev = (const float*)d_in[8];
    const float* b_ev = (const float*)d_in[9];
    const float* W_ef = (const float*)d_in[10];
    const float* b_ef = (const float*)d_in[11];
    const int* node_idx = (const int*)d_in[12];
    const int* edge_idx = (const int*)d_in[13];

    float* out = (float*)d_out;
    float* vfeat_out = out;
    float* efeat_out = out + (size_t)N_NODES * D;

    float* norm_v_ptr = nullptr;
    float* norm_e_ptr = nullptr;
    __nv_bfloat16* wh_ptr = nullptr;
    __nv_bfloat16* wl_ptr = nullptr;
    cudaGetSymbolAddress((void**)&norm_v_ptr, g_norm_v);
    cudaGetSymbolAddress((void**)&norm_e_ptr, g_norm_e);
    cudaGetSymbolAddress((void**)&wh_ptr, g_Wh);
    cudaGetSymbolAddress((void**)&wl_ptr, g_Wl);

    cudaFuncSetAttribute(gemm_bf16_kernel<true>,
                         cudaFuncAttributeMaxDynamicSharedMemorySize, SM_TOTAL);
    cudaFuncSetAttribute(gemm_bf16_kernel<false>,
                         cudaFuncAttributeMaxDynamicSharedMemorySize, SM_TOTAL);

    const size_t WSZ = (size_t)D * W_ROW_U16;  // per-matrix split size

    // 1. zero scratch + split weights (W_ve=0, W_ef=1, W_ev=2)
    zero_kernel<<<17500, 256>>>();
    wsplit_kernel<<<(3 * D * D + 255) / 256, 256>>>(W_ve, W_ef, W_ev);

    // 2. scatter nodes -> edges
    scatter_kernel<<<(N_INC * 32 + 255) / 256, 256>>>(
        vfeat, v_reg_weight, e_reg_sum, node_idx, edge_idx, norm_v_ptr);

    // 3+4. efeat_out = relu(norm_v @ W_ve^T + b_ve) + efeat @ W_ef^T + b_ef
    gemm_bf16_kernel<true><<<(N_HEDGES + 63) / 64, 256, SM_TOTAL>>>(
        norm_v_ptr, b_ve, wh_ptr + 0 * WSZ, wl_ptr + 0 * WSZ,
        efeat, b_ef, wh_ptr + 1 * WSZ, wl_ptr + 1 * WSZ,
        N_HEDGES, efeat_out);

    // 5. scatter edges -> nodes
    scatter_kernel<<<(N_INC * 32 + 255) / 256, 256>>>(
        efeat_out, e_reg_weight, v_reg_sum, edge_idx, node_idx, norm_e_ptr);

    // 6. vfeat_out = relu(norm_e @ W_ev^T + b_ev)
    gemm_bf16_kernel<false><<<(N_NODES + 63) / 64, 256, SM_TOTAL>>>(
        norm_e_ptr, b_ev, wh_ptr + 2 * WSZ, wl_ptr + 2 * WSZ,
        nullptr, nullptr, nullptr, nullptr,
        N_NODES, vfeat_out);
}

// round 5
// speedup vs baseline: 2.1193x; 1.4327x over previous
#include <cuda_runtime.h>
#include <cuda_bf16.h>
#include <cstdint>

#define N_NODES 100000
#define N_HEDGES 40000
#define N_INC 600000
#define D 128

#define PITCH_B 272
#define W_ROW_U16 136

// ---------------------------------------------------------------------------
// Scratch (allocation-free __device__ globals).
// ---------------------------------------------------------------------------
static __device__ float g_norm_v[(size_t)N_HEDGES * D];   // gather_e output
static __device__ float g_norm_e[(size_t)N_NODES * D];    // gather_v output
static __device__ __nv_bfloat16 g_Wh[3][D * W_ROW_U16];
static __device__ __nv_bfloat16 g_Wl[3][D * W_ROW_U16];

// CSR scratch
static __device__ int g_cnt_e[N_HEDGES];
static __device__ int g_cnt_v[N_NODES];
static __device__ int g_off_e[N_HEDGES + 1];
static __device__ int g_off_v[N_NODES + 1];
static __device__ int g_bsum_e[512];
static __device__ int g_bsum_v[512];
static __device__ int g_srt_e[N_INC];   // source node ids, grouped by hyperedge
static __device__ int g_srt_v[N_INC];   // source edge ids, grouped by node

// ---------------------------------------------------------------------------
// CSR build
// ---------------------------------------------------------------------------
__global__ void zero_cnt_kernel() {
    int i = blockIdx.x * blockDim.x + threadIdx.x;
    if (i < N_HEDGES) g_cnt_e[i] = 0;
    if (i < N_NODES) g_cnt_v[i] = 0;
}

__global__ void hist_kernel(const int* __restrict__ node_idx,
                            const int* __restrict__ edge_idx) {
    int i = blockIdx.x * blockDim.x + threadIdx.x;
    if (i >= N_INC) return;
    atomicAdd(&g_cnt_e[edge_idx[i]], 1);
    atomicAdd(&g_cnt_v[node_idx[i]], 1);
}

// 3-phase exclusive scan (2048 elems per block in phase A)
__global__ void scan_phaseA(const int* __restrict__ cnt, int* __restrict__ off,
                            int* __restrict__ bsum, int n) {
    __shared__ int sm[512];
    int t = threadIdx.x;
    int base = blockIdx.x * 2048 + t * 4;
    int v[4], s = 0;
    #pragma unroll
    for (int q = 0; q < 4; q++) {
        v[q] = (base + q < n) ? cnt[base + q] : 0;
        s += v[q];
    }
    sm[t] = s;
    __syncthreads();
    #pragma unroll
    for (int d = 1; d < 512; d <<= 1) {
        int x = (t >= d) ? sm[t - d] : 0;
        __syncthreads();
        sm[t] += x;
        __syncthreads();
    }
    int run = sm[t] - s;  // exclusive prefix of this thread within block
    #pragma unroll
    for (int q = 0; q < 4; q++) {
        if (base + q < n) off[base + q] = run;
        run += v[q];
    }
    if (t == 511) bsum[blockIdx.x] = sm[511];
}

__global__ void scan_phaseB(int* __restrict__ bsum, int nb, int* __restrict__ off_last) {
    __shared__ int sm[512];
    int t = threadIdx.x;
    int v = (t < nb) ? bsum[t] : 0;
    sm[t] = v;
    __syncthreads();
    #pragma unroll
    for (int d = 1; d < 512; d <<= 1) {
        int x = (t >= d) ? sm[t - d] : 0;
        __syncthreads();
        sm[t] += x;
        __syncthreads();
    }
    if (t < nb) bsum[t] = sm[t] - v;
    if (t == 511) *off_last = sm[511];
}

__global__ void scan_phaseC(int* __restrict__ off, const int* __restrict__ bsum, int n) {
    int i = blockIdx.x * blockDim.x + threadIdx.x;
    if (i < n) off[i] += bsum[i >> 11];
}

// Fill sorted source lists; uses cnt arrays as countdown cursors (ends at 0).
__global__ void fill_kernel(const int* __restrict__ node_idx,
                            const int* __restrict__ edge_idx) {
    int i = blockIdx.x * blockDim.x + threadIdx.x;
    if (i >= N_INC) return;
    int v = node_idx[i], e = edge_idx[i];
    int pe = atomicAdd(&g_cnt_e[e], -1) - 1;
    g_srt_e[g_off_e[e] + pe] = v;
    int pv = atomicAdd(&g_cnt_v[v], -1) - 1;
    g_srt_v[g_off_v[v] + pv] = e;
}

// ---------------------------------------------------------------------------
// Gather-reduce: out[d] = (sum_{s in seg(d)} src_w[s] * feat[s]) / dst_sum[d]
// One warp per destination; lane handles 4 dims (float4).
// ---------------------------------------------------------------------------
__global__ void __launch_bounds__(256) gather_kernel(
    const float* __restrict__ feat, const float* __restrict__ src_w,
    const float* __restrict__ dst_sum, const int* __restrict__ off,
    const int* __restrict__ srt, int n_dst, float* __restrict__ out)
{
    int d = (blockIdx.x * blockDim.x + threadIdx.x) >> 5;
    if (d >= n_dst) return;
    int lane = threadIdx.x & 31;
    int jb = __ldg(&off[d]);
    int je = __ldg(&off[d + 1]);

    float4 acc = make_float4(0.f, 0.f, 0.f, 0.f);
    const float4* f4 = reinterpret_cast<const float4*>(feat);

    int j = jb;
    for (; j + 2 <= je; j += 2) {
        int s0 = __ldg(&srt[j]);
        int s1 = __ldg(&srt[j + 1]);
        float w0 = __ldg(&src_w[s0]);
        float w1 = __ldg(&src_w[s1]);
        float4 a = __ldg(f4 + (size_t)s0 * 32 + lane);
        float4 b = __ldg(f4 + (size_t)s1 * 32 + lane);
        acc.x += w0 * a.x + w1 * b.x;
        acc.y += w0 * a.y + w1 * b.y;
        acc.z += w0 * a.z + w1 * b.z;
        acc.w += w0 * a.w + w1 * b.w;
    }
    if (j < je) {
        int s0 = __ldg(&srt[j]);
        float w0 = __ldg(&src_w[s0]);
        float4 a = __ldg(f4 + (size_t)s0 * 32 + lane);
        acc.x += w0 * a.x; acc.y += w0 * a.y;
        acc.z += w0 * a.z; acc.w += w0 * a.w;
    }

    float rinv = 1.0f / __ldg(&dst_sum[d]);
    acc.x *= rinv; acc.y *= rinv; acc.z *= rinv; acc.w *= rinv;
    reinterpret_cast<float4*>(out)[(size_t)d * 32 + lane] = acc;
}

// ---------------------------------------------------------------------------
// Weight split (bf16 hi/lo, [128][136] layout)
// ---------------------------------------------------------------------------
__global__ void wsplit_kernel(const float* __restrict__ W0,
                              const float* __restrict__ W1,
                              const float* __restrict__ W2) {
    int i = blockIdx.x * blockDim.x + threadIdx.x;
    if (i >= 3 * D * D) return;
    int w = i >> 14;
    int j = i & (D * D - 1);
    const float* W = (w == 0) ? W0 : (w == 1) ? W1 : W2;
    int n = j >> 7, k = j & 127;
    float x = W[j];
    __nv_bfloat16 hi = __float2bfloat16(x);
    __nv_bfloat16 lo = __float2bfloat16(x - __bfloat162float(hi));
    g_Wh[w][n * W_ROW_U16 + k] = hi;
    g_Wl[w][n * W_ROW_U16 + k] = lo;
}

// ---------------------------------------------------------------------------
// PTX helpers
// ---------------------------------------------------------------------------
__device__ __forceinline__ uint32_t smem_u32(const void* p) {
    uint32_t a;
    asm("{ .reg .u64 t; cvta.to.shared.u64 t, %1; cvt.u32.u64 %0, t; }"
        : "=r"(a) : "l"(p));
    return a;
}
__device__ __forceinline__ void ldm_x4(uint32_t* r, uint32_t addr) {
    asm volatile("ldmatrix.sync.aligned.m8n8.x4.shared.b16 {%0,%1,%2,%3}, [%4];"
                 : "=r"(r[0]), "=r"(r[1]), "=r"(r[2]), "=r"(r[3]) : "r"(addr));
}
__device__ __forceinline__ void mma_bf16(float* c, const uint32_t* a,
                                         uint32_t b0, uint32_t b1) {
    asm volatile("mma.sync.aligned.m16n8k16.row.col.f32.bf16.bf16.f32 "
                 "{%0,%1,%2,%3},{%4,%5,%6,%7},{%8,%9},{%0,%1,%2,%3};"
                 : "+f"(c[0]), "+f"(c[1]), "+f"(c[2]), "+f"(c[3])
                 : "r"(a[0]), "r"(a[1]), "r"(a[2]), "r"(a[3]), "r"(b0), "r"(b1));
}
__device__ __forceinline__ uint32_t pack_bf16x2(float x, float y) {
    __nv_bfloat16 hx = __float2bfloat16(x), hy = __float2bfloat16(y);
    return (uint32_t)__bfloat16_as_ushort(hx) | ((uint32_t)__bfloat16_as_ushort(hy) << 16);
}

#define SM_AHI 0
#define SM_ALO (SM_AHI + 64 * PITCH_B)
#define SM_WHI (SM_ALO + 64 * PITCH_B)
#define SM_WLO (SM_WHI + 128 * PITCH_B)
#define SM_TOTAL (SM_WLO + 128 * PITCH_B)   // 104448

// ---------------------------------------------------------------------------
// bf16x3 mma.sync GEMM (unchanged from round 4; known good).
// ---------------------------------------------------------------------------
template <bool FUSED>
__global__ void __launch_bounds__(256) gemm_bf16_kernel(
    const float* __restrict__ A0, const float* __restrict__ bias0,
    const __nv_bfloat16* __restrict__ Wh0, const __nv_bfloat16* __restrict__ Wl0,
    const float* __restrict__ A1, const float* __restrict__ bias1,
    const __nv_bfloat16* __restrict__ Wh1, const __nv_bfloat16* __restrict__ Wl1,
    int M, float* __restrict__ Out)
{
    extern __shared__ char smem[];
    const uint32_t sb = smem_u32(smem);
    const int tid = threadIdx.x;
    const int lane = tid & 31;
    const int warp = tid >> 5;
    const int wm = warp & 1;
    const int wn = warp >> 1;
    const int m_base = blockIdx.x * 64;

    float c[2][4][4];
    #pragma unroll
    for (int mf = 0; mf < 2; mf++)
        #pragma unroll
        for (int nt = 0; nt < 4; nt++)
            #pragma unroll
            for (int i = 0; i < 4; i++) c[mf][nt][i] = 0.f;

    const int rA = (lane & 7) + ((lane >> 3) & 1) * 8;
    const int kA = ((lane >> 4) & 1) * 8;
    const int rB = (lane & 7) + ((lane >> 4) & 1) * 8;
    const int kB = ((lane >> 3) & 1) * 8;
    const uint32_t aoff = (uint32_t)((wm * 32 + rA) * PITCH_B + kA * 2);
    const uint32_t boff = (uint32_t)((wn * 32 + rB) * PITCH_B + kB * 2);

    const int n_phases = FUSED ? 2 : 1;
    for (int phase = 0; phase < n_phases; phase++) {
        const float* A = phase ? A1 : A0;
        const uint4* wh4 = reinterpret_cast<const uint4*>(phase ? Wh1 : Wh0);
        const uint4* wl4 = reinterpret_cast<const uint4*>(phase ? Wl1 : Wl0);

        if (phase) __syncthreads();

        {
            uint4* dh = reinterpret_cast<uint4*>(smem + SM_WHI);
            uint4* dl = reinterpret_cast<uint4*>(smem + SM_WLO);
            #pragma unroll
            for (int i = tid; i < 128 * PITCH_B / 16; i += 256) {
                dh[i] = wh4[i];
                dl[i] = wl4[i];
            }
        }
        {
            int row = tid >> 2;
            int seg = tid & 3;
            int gm = m_base + row;
            float v[32];
            if (gm < M) {
                const float4* ap = reinterpret_cast<const float4*>(A)
                                   + (size_t)gm * 32 + seg * 8;
                #pragma unroll
                for (int q = 0; q < 8; q++) {
                    float4 f = ap[q];
                    v[4 * q] = f.x; v[4 * q + 1] = f.y;
                    v[4 * q + 2] = f.z; v[4 * q + 3] = f.w;
                }
            } else {
                #pragma unroll
                for (int q = 0; q < 32; q++) v[q] = 0.f;
            }
            uint32_t hp[16], lp[16];
            #pragma unroll
            for (int q = 0; q < 16; q++) {
                float x = v[2 * q], y = v[2 * q + 1];
                uint32_t h = pack_bf16x2(x, y);
                float hx = __bfloat162float(__ushort_as_bfloat16((unsigned short)(h & 0xFFFF)));
                float hy = __bfloat162float(__ushort_as_bfloat16((unsigned short)(h >> 16)));
                hp[q] = h;
                lp[q] = pack_bf16x2(x - hx, y - hy);
            }
            char* dst_h = smem + SM_AHI + row * PITCH_B + seg * 64;
            char* dst_l = smem + SM_ALO + row * PITCH_B + seg * 64;
            #pragma unroll
            for (int q = 0; q < 4; q++) {
                *reinterpret_cast<uint4*>(dst_h + 16 * q) =
                    make_uint4(hp[4 * q], hp[4 * q + 1], hp[4 * q + 2], hp[4 * q + 3]);
                *reinterpret_cast<uint4*>(dst_l + 16 * q) =
                    make_uint4(lp[4 * q], lp[4 * q + 1], lp[4 * q + 2], lp[4 * q + 3]);
            }
        }
        __syncthreads();

        #pragma unroll
        for (int kt = 0; kt < 8; kt++) {
            const uint32_t kb = kt * 32;
            uint32_t ah[2][4], al[2][4];
            ldm_x4(ah[0], sb + SM_AHI + aoff + kb);
            ldm_x4(ah[1], sb + SM_AHI + aoff + 16 * PITCH_B + kb);
            ldm_x4(al[0], sb + SM_ALO + aoff + kb);
            ldm_x4(al[1], sb + SM_ALO + aoff + 16 * PITCH_B + kb);
            uint32_t bh[8], bl[8];
            ldm_x4(&bh[0], sb + SM_WHI + boff + kb);
            ldm_x4(&bh[4], sb + SM_WHI + boff + 16 * PITCH_B + kb);
            ldm_x4(&bl[0], sb + SM_WLO + boff + kb);
            ldm_x4(&bl[4], sb + SM_WLO + boff + 16 * PITCH_B + kb);

            #pragma unroll
            for (int nt = 0; nt < 4; nt++) {
                uint32_t b0h = bh[2 * nt], b1h = bh[2 * nt + 1];
                uint32_t b0l = bl[2 * nt], b1l = bl[2 * nt + 1];
                #pragma unroll
                for (int mf = 0; mf < 2; mf++) {
                    mma_bf16(c[mf][nt], ah[mf], b0h, b1h);
                    mma_bf16(c[mf][nt], al[mf], b0h, b1h);
                    mma_bf16(c[mf][nt], ah[mf], b0l, b1l);
                }
            }
        }

        if (FUSED && phase == 0) {
            #pragma unroll
            for (int nt = 0; nt < 4; nt++) {
                int col = wn * 32 + nt * 8 + 2 * (lane & 3);
                float2 b = __ldg(reinterpret_cast<const float2*>(&bias0[col]));
                #pragma unroll
                for (int mf = 0; mf < 2; mf++) {
                    c[mf][nt][0] = fmaxf(c[mf][nt][0] + b.x, 0.f);
                    c[mf][nt][1] = fmaxf(c[mf][nt][1] + b.y, 0.f);
                    c[mf][nt][2] = fmaxf(c[mf][nt][2] + b.x, 0.f);
                    c[mf][nt][3] = fmaxf(c[mf][nt][3] + b.y, 0.f);
                }
            }
        }
    }

    const float* bias_f = FUSED ? bias1 : bias0;
    #pragma unroll
    for (int nt = 0; nt < 4; nt++) {
        int col = wn * 32 + nt * 8 + 2 * (lane & 3);
        float2 b = __ldg(reinterpret_cast<const float2*>(&bias_f[col]));
        #pragma unroll
        for (int mf = 0; mf < 2; mf++) {
            int row0 = m_base + wm * 32 + mf * 16 + (lane >> 2);
            float2 o01 = make_float2(c[mf][nt][0] + b.x, c[mf][nt][1] + b.y);
            float2 o23 = make_float2(c[mf][nt][2] + b.x, c[mf][nt][3] + b.y);
            if (!FUSED) {
                o01.x = fmaxf(o01.x, 0.f); o01.y = fmaxf(o01.y, 0.f);
                o23.x = fmaxf(o23.x, 0.f); o23.y = fmaxf(o23.y, 0.f);
            }
            if (row0 < M)
                *reinterpret_cast<float2*>(&Out[(size_t)row0 * D + col]) = o01;
            if (row0 + 8 < M)
                *reinterpret_cast<float2*>(&Out[(size_t)(row0 + 8) * D + col]) = o23;
        }
    }
}

extern "C" void kernel_launch(void* const* d_in, const int* in_sizes, int n_in,
                              void* d_out, int out_size) {
    (void)in_sizes; (void)n_in; (void)out_size;

    const float* vfeat = (const float*)d_in[0];
    const float* efeat = (const float*)d_in[1];
    const float* v_reg_weight = (const float*)d_in[2];
    const float* v_reg_sum    = (const float*)d_in[3];
    const float* e_reg_weight = (const float*)d_in[4];
    const float* e_reg_sum    = (const float*)d_in[5];
    const float* W_ve = (const float*)d_in[6];
    const float* b_ve = (const float*)d_in[7];
    const float* W_ev = (const float*)d_in[8];
    const float* b_ev = (const float*)d_in[9];
    const float* W_ef = (const float*)d_in[10];
    const float* b_ef = (const float*)d_in[11];
    const int* node_idx = (const int*)d_in[12];
    const int* edge_idx = (const int*)d_in[13];

    float* out = (float*)d_out;
    float* vfeat_out = out;
    float* efeat_out = out + (size_t)N_NODES * D;

    float *norm_v_ptr, *norm_e_ptr;
    __nv_bfloat16 *wh_ptr, *wl_ptr;
    int *off_e_ptr, *off_v_ptr, *srt_e_ptr, *srt_v_ptr, *bsum_e_ptr, *bsum_v_ptr;
    cudaGetSymbolAddress((void**)&norm_v_ptr, g_norm_v);
    cudaGetSymbolAddress((void**)&norm_e_ptr, g_norm_e);
    cudaGetSymbolAddress((void**)&wh_ptr, g_Wh);
    cudaGetSymbolAddress((void**)&wl_ptr, g_Wl);
    cudaGetSymbolAddress((void**)&off_e_ptr, g_off_e);
    cudaGetSymbolAddress((void**)&off_v_ptr, g_off_v);
    cudaGetSymbolAddress((void**)&srt_e_ptr, g_srt_e);
    cudaGetSymbolAddress((void**)&srt_v_ptr, g_srt_v);
    cudaGetSymbolAddress((void**)&bsum_e_ptr, g_bsum_e);
    cudaGetSymbolAddress((void**)&bsum_v_ptr, g_bsum_v);
    int* cnt_e_ptr;
    int* cnt_v_ptr;
    cudaGetSymbolAddress((void**)&cnt_e_ptr, g_cnt_e);
    cudaGetSymbolAddress((void**)&cnt_v_ptr, g_cnt_v);

    cudaFuncSetAttribute(gemm_bf16_kernel<true>,
                         cudaFuncAttributeMaxDynamicSharedMemorySize, SM_TOTAL);
    cudaFuncSetAttribute(gemm_bf16_kernel<false>,
                         cudaFuncAttributeMaxDynamicSharedMemorySize, SM_TOTAL);

    const size_t WSZ = (size_t)D * W_ROW_U16;
    const int NB_E = (N_HEDGES + 2047) / 2048;   // 20
    const int NB_V = (N_NODES + 2047) / 2048;    // 49

    // --- CSR build ---
    zero_cnt_kernel<<<(N_NODES + 255) / 256, 256>>>();
    hist_kernel<<<(N_INC + 255) / 256, 256>>>(node_idx, edge_idx);
    scan_phaseA<<<NB_E, 512>>>(cnt_e_ptr, off_e_ptr, bsum_e_ptr, N_HEDGES);
    scan_phaseB<<<1, 512>>>(bsum_e_ptr, NB_E, off_e_ptr + N_HEDGES);
    scan_phaseC<<<(N_HEDGES + 255) / 256, 256>>>(off_e_ptr, bsum_e_ptr, N_HEDGES);
    scan_phaseA<<<NB_V, 512>>>(cnt_v_ptr, off_v_ptr, bsum_v_ptr, N_NODES);
    scan_phaseB<<<1, 512>>>(bsum_v_ptr, NB_V, off_v_ptr + N_NODES);
    scan_phaseC<<<(N_NODES + 255) / 256, 256>>>(off_v_ptr, bsum_v_ptr, N_NODES);
    fill_kernel<<<(N_INC + 255) / 256, 256>>>(node_idx, edge_idx);

    // --- weight split ---
    wsplit_kernel<<<(3 * D * D + 255) / 256, 256>>>(W_ve, W_ef, W_ev);

    // --- g1: gather nodes -> edges ---
    gather_kernel<<<(N_HEDGES * 32 + 255) / 256, 256>>>(
        vfeat, v_reg_weight, e_reg_sum, off_e_ptr, srt_e_ptr, N_HEDGES, norm_v_ptr);

    // efeat_out = relu(norm_v @ W_ve^T + b_ve) + efeat @ W_ef^T + b_ef
    gemm_bf16_kernel<true><<<(N_HEDGES + 63) / 64, 256, SM_TOTAL>>>(
        norm_v_ptr, b_ve, wh_ptr + 0 * WSZ, wl_ptr + 0 * WSZ,
        efeat, b_ef, wh_ptr + 1 * WSZ, wl_ptr + 1 * WSZ,
        N_HEDGES, efeat_out);

    // --- g2: gather edges -> nodes ---
    gather_kernel<<<(N_NODES * 32 + 255) / 256, 256>>>(
        efeat_out, e_reg_weight, v_reg_sum, off_v_ptr, srt_v_ptr, N_NODES, norm_e_ptr);

    // vfeat_out = relu(norm_e @ W_ev^T + b_ev)
    gemm_bf16_kernel<false><<<(N_NODES + 63) / 64, 256, SM_TOTAL>>>(
        norm_e_ptr, b_ev, wh_ptr + 2 * WSZ, wl_ptr + 2 * WSZ,
        nullptr, nullptr, nullptr, nullptr,
        N_NODES, vfeat_out);
}

// round 6
// speedup vs baseline: 2.2263x; 1.0505x over previous
#include <cuda_runtime.h>
#include <cuda_bf16.h>
#include <cstdint>

#define N_NODES 100000
#define N_HEDGES 40000
#define N_INC 600000
#define D 128

#define PITCH_B 272
#define W_ROW_U16 136

#define NB_E ((N_HEDGES + 2047) / 2048)   // 20
#define NB_V ((N_NODES + 2047) / 2048)    // 49
#define HIST_BLOCKS ((N_INC + 255) / 256) // 2344
#define WSPLIT_BLOCKS ((3 * D * D + 255) / 256) // 192

// ---------------------------------------------------------------------------
// Scratch (allocation-free __device__ globals; zero-initialized at load).
// ---------------------------------------------------------------------------
static __device__ float g_norm_v[(size_t)N_HEDGES * D];
static __device__ float g_norm_e[(size_t)N_NODES * D];
static __device__ __nv_bfloat16 g_Wh[3][D * W_ROW_U16];
static __device__ __nv_bfloat16 g_Wl[3][D * W_ROW_U16];

// CSR scratch. INVARIANT: g_cnt_* start at 0 (static zero-init) and fill_kernel's
// countdown atomics return them to exactly 0 -> no zeroing kernel needed.
static __device__ int g_cnt_e[N_HEDGES];
static __device__ int g_cnt_v[N_NODES];
static __device__ int g_off_e[N_HEDGES + 1];
static __device__ int g_off_v[N_NODES + 1];
static __device__ int g_bsum_e[512];
static __device__ int g_bsum_v[512];
static __device__ int g_srt_e[N_INC];
static __device__ int g_srt_v[N_INC];

// ---------------------------------------------------------------------------
// Fused histogram + weight-split (disjoint block ranges).
// ---------------------------------------------------------------------------
__global__ void hist_wsplit_kernel(const int* __restrict__ node_idx,
                                   const int* __restrict__ edge_idx,
                                   const float* __restrict__ W0,
                                   const float* __restrict__ W1,
                                   const float* __restrict__ W2) {
    int b = blockIdx.x;
    if (b < HIST_BLOCKS) {
        int i = b * 256 + threadIdx.x;
        if (i < N_INC) {
            atomicAdd(&g_cnt_e[edge_idx[i]], 1);
            atomicAdd(&g_cnt_v[node_idx[i]], 1);
        }
    } else {
        int i = (b - HIST_BLOCKS) * 256 + threadIdx.x;
        if (i < 3 * D * D) {
            int w = i >> 14;
            int j = i & (D * D - 1);
            const float* W = (w == 0) ? W0 : (w == 1) ? W1 : W2;
            int n = j >> 7, k = j & 127;
            float x = W[j];
            __nv_bfloat16 hi = __float2bfloat16(x);
            __nv_bfloat16 lo = __float2bfloat16(x - __bfloat162float(hi));
            g_Wh[w][n * W_ROW_U16 + k] = hi;
            g_Wl[w][n * W_ROW_U16 + k] = lo;
        }
    }
}

// ---------------------------------------------------------------------------
// 3-phase exclusive scan, both arrays per launch.
// ---------------------------------------------------------------------------
__global__ void scan_phaseA2() {
    __shared__ int sm[512];
    int b = blockIdx.x;
    const int* cnt; int* off; int* bsum; int n; int lb;
    if (b < NB_E) { cnt = g_cnt_e; off = g_off_e; bsum = g_bsum_e; n = N_HEDGES; lb = b; }
    else          { cnt = g_cnt_v; off = g_off_v; bsum = g_bsum_v; n = N_NODES;  lb = b - NB_E; }

    int t = threadIdx.x;
    int base = lb * 2048 + t * 4;
    int v[4], s = 0;
    #pragma unroll
    for (int q = 0; q < 4; q++) {
        v[q] = (base + q < n) ? cnt[base + q] : 0;
        s += v[q];
    }
    sm[t] = s;
    __syncthreads();
    #pragma unroll
    for (int d = 1; d < 512; d <<= 1) {
        int x = (t >= d) ? sm[t - d] : 0;
        __syncthreads();
        sm[t] += x;
        __syncthreads();
    }
    int run = sm[t] - s;
    #pragma unroll
    for (int q = 0; q < 4; q++) {
        if (base + q < n) off[base + q] = run;
        run += v[q];
    }
    if (t == 511) bsum[lb] = sm[511];
}

__device__ __forceinline__ void scanB_body(int* bsum, int nb, int* off_last) {
    __shared__ int sm[512];
    int t = threadIdx.x;
    int v = (t < nb) ? bsum[t] : 0;
    sm[t] = v;
    __syncthreads();
    #pragma unroll
    for (int d = 1; d < 512; d <<= 1) {
        int x = (t >= d) ? sm[t - d] : 0;
        __syncthreads();
        sm[t] += x;
        __syncthreads();
    }
    if (t < nb) bsum[t] = sm[t] - v;
    if (t == 511) *off_last = sm[511];
}

__global__ void scan_phaseB2() {
    if (blockIdx.x == 0) scanB_body(g_bsum_e, NB_E, &g_off_e[N_HEDGES]);
    else                 scanB_body(g_bsum_v, NB_V, &g_off_v[N_NODES]);
}

__global__ void scan_phaseC2() {
    int i = blockIdx.x * blockDim.x + threadIdx.x;
    if (i < N_HEDGES) g_off_e[i] += g_bsum_e[i >> 11];
    int j = i - N_HEDGES;
    if (j >= 0 && j < N_NODES) g_off_v[j] += g_bsum_v[j >> 11];
}

// Fill sorted source lists; countdown cursors end at exactly 0 (invariant).
__global__ void fill_kernel(const int* __restrict__ node_idx,
                            const int* __restrict__ edge_idx) {
    int i = blockIdx.x * blockDim.x + threadIdx.x;
    if (i >= N_INC) return;
    int v = node_idx[i], e = edge_idx[i];
    int pe = atomicAdd(&g_cnt_e[e], -1) - 1;
    g_srt_e[g_off_e[e] + pe] = v;
    int pv = atomicAdd(&g_cnt_v[v], -1) - 1;
    g_srt_v[g_off_v[v] + pv] = e;
}

// ---------------------------------------------------------------------------
// Gather-reduce: out[d] = (sum_{s in seg(d)} src_w[s] * feat[s]) / dst_sum[d]
// ---------------------------------------------------------------------------
__global__ void __launch_bounds__(256) gather_kernel(
    const float* __restrict__ feat, const float* __restrict__ src_w,
    const float* __restrict__ dst_sum, const int* __restrict__ off,
    const int* __restrict__ srt, int n_dst, float* __restrict__ out)
{
    int d = (blockIdx.x * blockDim.x + threadIdx.x) >> 5;
    if (d >= n_dst) return;
    int lane = threadIdx.x & 31;
    int jb = __ldg(&off[d]);
    int je = __ldg(&off[d + 1]);

    float4 acc = make_float4(0.f, 0.f, 0.f, 0.f);
    const float4* f4 = reinterpret_cast<const float4*>(feat);

    int j = jb;
    for (; j + 2 <= je; j += 2) {
        int s0 = __ldg(&srt[j]);
        int s1 = __ldg(&srt[j + 1]);
        float w0 = __ldg(&src_w[s0]);
        float w1 = __ldg(&src_w[s1]);
        float4 a = __ldg(f4 + (size_t)s0 * 32 + lane);
        float4 b = __ldg(f4 + (size_t)s1 * 32 + lane);
        acc.x += w0 * a.x + w1 * b.x;
        acc.y += w0 * a.y + w1 * b.y;
        acc.z += w0 * a.z + w1 * b.z;
        acc.w += w0 * a.w + w1 * b.w;
    }
    if (j < je) {
        int s0 = __ldg(&srt[j]);
        float w0 = __ldg(&src_w[s0]);
        float4 a = __ldg(f4 + (size_t)s0 * 32 + lane);
        acc.x += w0 * a.x; acc.y += w0 * a.y;
        acc.z += w0 * a.z; acc.w += w0 * a.w;
    }

    float rinv = 1.0f / __ldg(&dst_sum[d]);
    acc.x *= rinv; acc.y *= rinv; acc.z *= rinv; acc.w *= rinv;
    reinterpret_cast<float4*>(out)[(size_t)d * 32 + lane] = acc;
}

// ---------------------------------------------------------------------------
// PTX helpers
// ---------------------------------------------------------------------------
__device__ __forceinline__ uint32_t smem_u32(const void* p) {
    uint32_t a;
    asm("{ .reg .u64 t; cvta.to.shared.u64 t, %1; cvt.u32.u64 %0, t; }"
        : "=r"(a) : "l"(p));
    return a;
}
__device__ __forceinline__ void ldm_x4(uint32_t* r, uint32_t addr) {
    asm volatile("ldmatrix.sync.aligned.m8n8.x4.shared.b16 {%0,%1,%2,%3}, [%4];"
                 : "=r"(r[0]), "=r"(r[1]), "=r"(r[2]), "=r"(r[3]) : "r"(addr));
}
__device__ __forceinline__ void mma_bf16(float* c, const uint32_t* a,
                                         uint32_t b0, uint32_t b1) {
    asm volatile("mma.sync.aligned.m16n8k16.row.col.f32.bf16.bf16.f32 "
                 "{%0,%1,%2,%3},{%4,%5,%6,%7},{%8,%9},{%0,%1,%2,%3};"
                 : "+f"(c[0]), "+f"(c[1]), "+f"(c[2]), "+f"(c[3])
                 : "r"(a[0]), "r"(a[1]), "r"(a[2]), "r"(a[3]), "r"(b0), "r"(b1));
}
__device__ __forceinline__ uint32_t pack_bf16x2(float x, float y) {
    __nv_bfloat16 hx = __float2bfloat16(x), hy = __float2bfloat16(y);
    return (uint32_t)__bfloat16_as_ushort(hx) | ((uint32_t)__bfloat16_as_ushort(hy) << 16);
}
__device__ __forceinline__ void cp_async16(uint32_t saddr, const void* g) {
    asm volatile("cp.async.ca.shared.global [%0], [%1], 16;"
                 :: "r"(saddr), "l"(g) : "memory");
}
#define CP_COMMIT() asm volatile("cp.async.commit_group;" ::: "memory")
#define CP_WAIT0()  asm volatile("cp.async.wait_group 0;" ::: "memory")

#define SM_AHI 0
#define SM_ALO (SM_AHI + 64 * PITCH_B)
#define SM_WHI (SM_ALO + 64 * PITCH_B)
#define SM_WLO (SM_WHI + 128 * PITCH_B)
#define SM_TOTAL (SM_WLO + 128 * PITCH_B)   // 104448

// ---------------------------------------------------------------------------
// bf16x3 mma.sync GEMM; W staged via cp.async overlapped with A convert.
// ---------------------------------------------------------------------------
template <bool FUSED>
__global__ void __launch_bounds__(256) gemm_bf16_kernel(
    const float* __restrict__ A0, const float* __restrict__ bias0,
    const __nv_bfloat16* __restrict__ Wh0, const __nv_bfloat16* __restrict__ Wl0,
    const float* __restrict__ A1, const float* __restrict__ bias1,
    const __nv_bfloat16* __restrict__ Wh1, const __nv_bfloat16* __restrict__ Wl1,
    int M, float* __restrict__ Out)
{
    extern __shared__ char smem[];
    const uint32_t sb = smem_u32(smem);
    const int tid = threadIdx.x;
    const int lane = tid & 31;
    const int warp = tid >> 5;
    const int wm = warp & 1;
    const int wn = warp >> 1;
    const int m_base = blockIdx.x * 64;

    float c[2][4][4];
    #pragma unroll
    for (int mf = 0; mf < 2; mf++)
        #pragma unroll
        for (int nt = 0; nt < 4; nt++)
            #pragma unroll
            for (int i = 0; i < 4; i++) c[mf][nt][i] = 0.f;

    const int rA = (lane & 7) + ((lane >> 3) & 1) * 8;
    const int kA = ((lane >> 4) & 1) * 8;
    const int rB = (lane & 7) + ((lane >> 4) & 1) * 8;
    const int kB = ((lane >> 3) & 1) * 8;
    const uint32_t aoff = (uint32_t)((wm * 32 + rA) * PITCH_B + kA * 2);
    const uint32_t boff = (uint32_t)((wn * 32 + rB) * PITCH_B + kB * 2);

    const int n_phases = FUSED ? 2 : 1;
    for (int phase = 0; phase < n_phases; phase++) {
        const float* A = phase ? A1 : A0;
        const char* whg = reinterpret_cast<const char*>(phase ? Wh1 : Wh0);
        const char* wlg = reinterpret_cast<const char*>(phase ? Wl1 : Wl0);

        if (phase) __syncthreads();

        // Issue async W hi/lo copies first (128*272B each = 2176 x 16B).
        #pragma unroll
        for (int i = tid; i < 2176; i += 256) {
            cp_async16(sb + SM_WHI + i * 16, whg + i * 16);
            cp_async16(sb + SM_WLO + i * 16, wlg + i * 16);
        }
        CP_COMMIT();

        // A staging overlapped under the cp.async: load f32, split bf16 hi/lo.
        {
            int row = tid >> 2;
            int seg = tid & 3;
            int gm = m_base + row;
            float v[32];
            if (gm < M) {
                const float4* ap = reinterpret_cast<const float4*>(A)
                                   + (size_t)gm * 32 + seg * 8;
                #pragma unroll
                for (int q = 0; q < 8; q++) {
                    float4 f = ap[q];
                    v[4 * q] = f.x; v[4 * q + 1] = f.y;
                    v[4 * q + 2] = f.z; v[4 * q + 3] = f.w;
                }
            } else {
                #pragma unroll
                for (int q = 0; q < 32; q++) v[q] = 0.f;
            }
            uint32_t hp[16], lp[16];
            #pragma unroll
            for (int q = 0; q < 16; q++) {
                float x = v[2 * q], y = v[2 * q + 1];
                uint32_t h = pack_bf16x2(x, y);
                float hx = __bfloat162float(__ushort_as_bfloat16((unsigned short)(h & 0xFFFF)));
                float hy = __bfloat162float(__ushort_as_bfloat16((unsigned short)(h >> 16)));
                hp[q] = h;
                lp[q] = pack_bf16x2(x - hx, y - hy);
            }
            char* dst_h = smem + SM_AHI + row * PITCH_B + seg * 64;
            char* dst_l = smem + SM_ALO + row * PITCH_B + seg * 64;
            #pragma unroll
            for (int q = 0; q < 4; q++) {
                *reinterpret_cast<uint4*>(dst_h + 16 * q) =
                    make_uint4(hp[4 * q], hp[4 * q + 1], hp[4 * q + 2], hp[4 * q + 3]);
                *reinterpret_cast<uint4*>(dst_l + 16 * q) =
                    make_uint4(lp[4 * q], lp[4 * q + 1], lp[4 * q + 2], lp[4 * q + 3]);
            }
        }
        CP_WAIT0();
        __syncthreads();

        #pragma unroll
        for (int kt = 0; kt < 8; kt++) {
            const uint32_t kb = kt * 32;
            uint32_t ah[2][4], al[2][4];
            ldm_x4(ah[0], sb + SM_AHI + aoff + kb);
            ldm_x4(ah[1], sb + SM_AHI + aoff + 16 * PITCH_B + kb);
            ldm_x4(al[0], sb + SM_ALO + aoff + kb);
            ldm_x4(al[1], sb + SM_ALO + aoff + 16 * PITCH_B + kb);
            uint32_t bh[8], bl[8];
            ldm_x4(&bh[0], sb + SM_WHI + boff + kb);
            ldm_x4(&bh[4], sb + SM_WHI + boff + 16 * PITCH_B + kb);
            ldm_x4(&bl[0], sb + SM_WLO + boff + kb);
            ldm_x4(&bl[4], sb + SM_WLO + boff + 16 * PITCH_B + kb);

            #pragma unroll
            for (int nt = 0; nt < 4; nt++) {
                uint32_t b0h = bh[2 * nt], b1h = bh[2 * nt + 1];
                uint32_t b0l = bl[2 * nt], b1l = bl[2 * nt + 1];
                #pragma unroll
                for (int mf = 0; mf < 2; mf++) {
                    mma_bf16(c[mf][nt], ah[mf], b0h, b1h);
                    mma_bf16(c[mf][nt], al[mf], b0h, b1h);
                    mma_bf16(c[mf][nt], ah[mf], b0l, b1l);
                }
            }
        }

        if (FUSED && phase == 0) {
            #pragma unroll
            for (int nt = 0; nt < 4; nt++) {
                int col = wn * 32 + nt * 8 + 2 * (lane & 3);
                float2 b = __ldg(reinterpret_cast<const float2*>(&bias0[col]));
                #pragma unroll
                for (int mf = 0; mf < 2; mf++) {
                    c[mf][nt][0] = fmaxf(c[mf][nt][0] + b.x, 0.f);
                    c[mf][nt][1] = fmaxf(c[mf][nt][1] + b.y, 0.f);
                    c[mf][nt][2] = fmaxf(c[mf][nt][2] + b.x, 0.f);
                    c[mf][nt][3] = fmaxf(c[mf][nt][3] + b.y, 0.f);
                }
            }
        }
    }

    const float* bias_f = FUSED ? bias1 : bias0;
    #pragma unroll
    for (int nt = 0; nt < 4; nt++) {
        int col = wn * 32 + nt * 8 + 2 * (lane & 3);
        float2 b = __ldg(reinterpret_cast<const float2*>(&bias_f[col]));
        #pragma unroll
        for (int mf = 0; mf < 2; mf++) {
            int row0 = m_base + wm * 32 + mf * 16 + (lane >> 2);
            float2 o01 = make_float2(c[mf][nt][0] + b.x, c[mf][nt][1] + b.y);
            float2 o23 = make_float2(c[mf][nt][2] + b.x, c[mf][nt][3] + b.y);
            if (!FUSED) {
                o01.x = fmaxf(o01.x, 0.f); o01.y = fmaxf(o01.y, 0.f);
                o23.x = fmaxf(o23.x, 0.f); o23.y = fmaxf(o23.y, 0.f);
            }
            if (row0 < M)
                *reinterpret_cast<float2*>(&Out[(size_t)row0 * D + col]) = o01;
            if (row0 + 8 < M)
                *reinterpret_cast<float2*>(&Out[(size_t)(row0 + 8) * D + col]) = o23;
        }
    }
}

extern "C" void kernel_launch(void* const* d_in, const int* in_sizes, int n_in,
                              void* d_out, int out_size) {
    (void)in_sizes; (void)n_in; (void)out_size;

    const float* vfeat = (const float*)d_in[0];
    const float* efeat = (const float*)d_in[1];
    const float* v_reg_weight = (const float*)d_in[2];
    const float* v_reg_sum    = (const float*)d_in[3];
    const float* e_reg_weight = (const float*)d_in[4];
    const float* e_reg_sum    = (const float*)d_in[5];
    const float* W_ve = (const float*)d_in[6];
    const float* b_ve = (const float*)d_in[7];
    const float* W_ev = (const float*)d_in[8];
    const float* b_ev = (const float*)d_in[9];
    const float* W_ef = (const float*)d_in[10];
    const float* b_ef = (const float*)d_in[11];
    const int* node_idx = (const int*)d_in[12];
    const int* edge_idx = (const int*)d_in[13];

    float* out = (float*)d_out;
    float* vfeat_out = out;
    float* efeat_out = out + (size_t)N_NODES * D;

    float *norm_v_ptr, *norm_e_ptr;
    __nv_bfloat16 *wh_ptr, *wl_ptr;
    int *off_e_ptr, *off_v_ptr, *srt_e_ptr, *srt_v_ptr;
    cudaGetSymbolAddress((void**)&norm_v_ptr, g_norm_v);
    cudaGetSymbolAddress((void**)&norm_e_ptr, g_norm_e);
    cudaGetSymbolAddress((void**)&wh_ptr, g_Wh);
    cudaGetSymbolAddress((void**)&wl_ptr, g_Wl);
    cudaGetSymbolAddress((void**)&off_e_ptr, g_off_e);
    cudaGetSymbolAddress((void**)&off_v_ptr, g_off_v);
    cudaGetSymbolAddress((void**)&srt_e_ptr, g_srt_e);
    cudaGetSymbolAddress((void**)&srt_v_ptr, g_srt_v);

    cudaFuncSetAttribute(gemm_bf16_kernel<true>,
                         cudaFuncAttributeMaxDynamicSharedMemorySize, SM_TOTAL);
    cudaFuncSetAttribute(gemm_bf16_kernel<false>,
                         cudaFuncAttributeMaxDynamicSharedMemorySize, SM_TOTAL);

    const size_t WSZ = (size_t)D * W_ROW_U16;

    // --- CSR build + weight split (5 launches) ---
    hist_wsplit_kernel<<<HIST_BLOCKS + WSPLIT_BLOCKS, 256>>>(
        node_idx, edge_idx, W_ve, W_ef, W_ev);
    scan_phaseA2<<<NB_E + NB_V, 512>>>();
    scan_phaseB2<<<2, 512>>>();
    scan_phaseC2<<<(N_HEDGES + N_NODES + 255) / 256, 256>>>();
    fill_kernel<<<(N_INC + 255) / 256, 256>>>(node_idx, edge_idx);

    // --- g1: gather nodes -> edges ---
    gather_kernel<<<(N_HEDGES * 32 + 255) / 256, 256>>>(
        vfeat, v_reg_weight, e_reg_sum, off_e_ptr, srt_e_ptr, N_HEDGES, norm_v_ptr);

    // efeat_out = relu(norm_v @ W_ve^T + b_ve) + efeat @ W_ef^T + b_ef
    gemm_bf16_kernel<true><<<(N_HEDGES + 63) / 64, 256, SM_TOTAL>>>(
        norm_v_ptr, b_ve, wh_ptr + 0 * WSZ, wl_ptr + 0 * WSZ,
        efeat, b_ef, wh_ptr + 1 * WSZ, wl_ptr + 1 * WSZ,
        N_HEDGES, efeat_out);

    // --- g2: gather edges -> nodes ---
    gather_kernel<<<(N_NODES * 32 + 255) / 256, 256>>>(
        efeat_out, e_reg_weight, v_reg_sum, off_v_ptr, srt_v_ptr, N_NODES, norm_e_ptr);

    // vfeat_out = relu(norm_e @ W_ev^T + b_ev)
    gemm_bf16_kernel<false><<<(N_NODES + 63) / 64, 256, SM_TOTAL>>>(
        norm_e_ptr, b_ev, wh_ptr + 2 * WSZ, wl_ptr + 2 * WSZ,
        nullptr, nullptr, nullptr, nullptr,
        N_NODES, vfeat_out);
}

// round 8
// speedup vs baseline: 2.3444x; 1.0530x over previous
#include <cuda_runtime.h>
#include <cuda_bf16.h>
#include <cstdint>

#define N_NODES 100000
#define N_HEDGES 40000
#define N_INC 600000
#define D 128

#define PITCH_B 272
#define W_ROW_U16 136

#define NB_E ((N_HEDGES + 2047) / 2048)   // 20
#define NB_V ((N_NODES + 2047) / 2048)    // 49
#define HIST_BLOCKS ((N_INC + 255) / 256) // 2344
#define WSPLIT_BLOCKS ((3 * D * D + 255) / 256) // 192

#define NSM 148
#define NCTA_PLAIN (2 * NSM)   // 296
#define NCTA_FUSED NSM         // 148

// ---------------------------------------------------------------------------
// Scratch (allocation-free __device__ globals; zero-initialized at load).
// ---------------------------------------------------------------------------
static __device__ float g_norm_v[(size_t)N_HEDGES * D];
static __device__ float g_norm_e[(size_t)N_NODES * D];
static __device__ __nv_bfloat16 g_Wh[3][D * W_ROW_U16];
static __device__ __nv_bfloat16 g_Wl[3][D * W_ROW_U16];

// CSR scratch. INVARIANT: g_cnt_* start at 0 and fill_kernel's countdown
// atomics return them to exactly 0 -> no zeroing needed between calls.
static __device__ int g_cnt_e[N_HEDGES];
static __device__ int g_cnt_v[N_NODES];
static __device__ int g_off_e[N_HEDGES + 1];
static __device__ int g_off_v[N_NODES + 1];
static __device__ int g_bsum_e[NB_E];
static __device__ int g_bsum_v[NB_V];
static __device__ int g_srt_e[N_INC];
static __device__ int g_srt_v[N_INC];

// ---------------------------------------------------------------------------
// Fused histogram + weight-split (disjoint block ranges).
// ---------------------------------------------------------------------------
__global__ void hist_wsplit_kernel(const int* __restrict__ node_idx,
                                   const int* __restrict__ edge_idx,
                                   const float* __restrict__ W0,
                                   const float* __restrict__ W1,
                                   const float* __restrict__ W2) {
    int b = blockIdx.x;
    if (b < HIST_BLOCKS) {
        int i = b * 256 + threadIdx.x;
        if (i < N_INC) {
            atomicAdd(&g_cnt_e[edge_idx[i]], 1);
            atomicAdd(&g_cnt_v[node_idx[i]], 1);
        }
    } else {
        int i = (b - HIST_BLOCKS) * 256 + threadIdx.x;
        if (i < 3 * D * D) {
            int w = i >> 14;
            int j = i & (D * D - 1);
            const float* W = (w == 0) ? W0 : (w == 1) ? W1 : W2;
            int n = j >> 7, k = j & 127;
            float x = W[j];
            __nv_bfloat16 hi = __float2bfloat16(x);
            __nv_bfloat16 lo = __float2bfloat16(x - __bfloat162float(hi));
            g_Wh[w][n * W_ROW_U16 + k] = hi;
            g_Wl[w][n * W_ROW_U16 + k] = lo;
        }
    }
}

// ---------------------------------------------------------------------------
// Scan phase A: per-2048-block exclusive scan, block totals to bsum.
// ---------------------------------------------------------------------------
__global__ void scan_phaseA2() {
    __shared__ int sm[512];
    int b = blockIdx.x;
    const int* cnt; int* off; int* bsum; int n; int lb;
    if (b < NB_E) { cnt = g_cnt_e; off = g_off_e; bsum = g_bsum_e; n = N_HEDGES; lb = b; }
    else          { cnt = g_cnt_v; off = g_off_v; bsum = g_bsum_v; n = N_NODES;  lb = b - NB_E; }

    int t = threadIdx.x;
    int base = lb * 2048 + t * 4;
    int v[4], s = 0;
    #pragma unroll
    for (int q = 0; q < 4; q++) {
        v[q] = (base + q < n) ? cnt[base + q] : 0;
        s += v[q];
    }
    sm[t] = s;
    __syncthreads();
    #pragma unroll
    for (int d = 1; d < 512; d <<= 1) {
        int x = (t >= d) ? sm[t - d] : 0;
        __syncthreads();
        sm[t] += x;
        __syncthreads();
    }
    int run = sm[t] - s;
    #pragma unroll
    for (int q = 0; q < 4; q++) {
        if (base + q < n) off[base + q] = run;
        run += v[q];
    }
    if (t == 511) bsum[lb] = sm[511];
}

// Phase C: each block locally scans the tiny bsum arrays (totals == N_INC by
// construction, so no separate phase B needed).
__global__ void scan_phaseC3() {
    __shared__ int pe[NB_E], pv[NB_V];
    int t = threadIdx.x;
    if (t < NB_E) pe[t] = g_bsum_e[t];
    else if (t < NB_E + NB_V) pv[t - NB_E] = g_bsum_v[t - NB_E];
    __syncthreads();
    if (t == 0) {
        int run = 0;
        #pragma unroll
        for (int i = 0; i < NB_E; i++) { int x = pe[i]; pe[i] = run; run += x; }
    } else if (t == 32) {
        int run = 0;
        #pragma unroll
        for (int i = 0; i < NB_V; i++) { int x = pv[i]; pv[i] = run; run += x; }
    }
    __syncthreads();
    int i = blockIdx.x * blockDim.x + t;
    if (i < N_HEDGES) g_off_e[i] += pe[i >> 11];
    int j = i - N_HEDGES;
    if (j >= 0 && j < N_NODES) g_off_v[j] += pv[j >> 11];
    if (i == 0) { g_off_e[N_HEDGES] = N_INC; g_off_v[N_NODES] = N_INC; }
}

// Fill sorted source lists; countdown cursors end at exactly 0 (invariant).
__global__ void fill_kernel(const int* __restrict__ node_idx,
                            const int* __restrict__ edge_idx) {
    int i = blockIdx.x * blockDim.x + threadIdx.x;
    if (i >= N_INC) return;
    int v = node_idx[i], e = edge_idx[i];
    int pe = atomicAdd(&g_cnt_e[e], -1) - 1;
    g_srt_e[g_off_e[e] + pe] = v;
    int pv = atomicAdd(&g_cnt_v[v], -1) - 1;
    g_srt_v[g_off_v[v] + pv] = e;
}

// ---------------------------------------------------------------------------
// Gather-reduce: out[d] = (sum_{s in seg(d)} src_w[s] * feat[s]) / dst_sum[d]
// ---------------------------------------------------------------------------
__global__ void __launch_bounds__(256) gather_kernel(
    const float* __restrict__ feat, const float* __restrict__ src_w,
    const float* __restrict__ dst_sum, const int* __restrict__ off,
    const int* __restrict__ srt, int n_dst, float* __restrict__ out)
{
    int d = (blockIdx.x * blockDim.x + threadIdx.x) >> 5;
    if (d >= n_dst) return;
    int lane = threadIdx.x & 31;
    int jb = __ldg(&off[d]);
    int je = __ldg(&off[d + 1]);

    float4 acc = make_float4(0.f, 0.f, 0.f, 0.f);
    const float4* f4 = reinterpret_cast<const float4*>(feat);

    int j = jb;
    for (; j + 2 <= je; j += 2) {
        int s0 = __ldg(&srt[j]);
        int s1 = __ldg(&srt[j + 1]);
        float w0 = __ldg(&src_w[s0]);
        float w1 = __ldg(&src_w[s1]);
        float4 a = __ldg(f4 + (size_t)s0 * 32 + lane);
        float4 b = __ldg(f4 + (size_t)s1 * 32 + lane);
        acc.x += w0 * a.x + w1 * b.x;
        acc.y += w0 * a.y + w1 * b.y;
        acc.z += w0 * a.z + w1 * b.z;
        acc.w += w0 * a.w + w1 * b.w;
    }
    if (j < je) {
        int s0 = __ldg(&srt[j]);
        float w0 = __ldg(&src_w[s0]);
        float4 a = __ldg(f4 + (size_t)s0 * 32 + lane);
        acc.x += w0 * a.x; acc.y += w0 * a.y;
        acc.z += w0 * a.z; acc.w += w0 * a.w;
    }

    float rinv = 1.0f / __ldg(&dst_sum[d]);
    acc.x *= rinv; acc.y *= rinv; acc.z *= rinv; acc.w *= rinv;
    reinterpret_cast<float4*>(out)[(size_t)d * 32 + lane] = acc;
}

// ---------------------------------------------------------------------------
// PTX helpers
// ---------------------------------------------------------------------------
__device__ __forceinline__ uint32_t smem_u32(const void* p) {
    uint32_t a;
    asm("{ .reg .u64 t; cvta.to.shared.u64 t, %1; cvt.u32.u64 %0, t; }"
        : "=r"(a) : "l"(p));
    return a;
}
__device__ __forceinline__ void ldm_x4(uint32_t* r, uint32_t addr) {
    asm volatile("ldmatrix.sync.aligned.m8n8.x4.shared.b16 {%0,%1,%2,%3}, [%4];"
                 : "=r"(r[0]), "=r"(r[1]), "=r"(r[2]), "=r"(r[3]) : "r"(addr));
}
__device__ __forceinline__ void mma_bf16(float* c, const uint32_t* a,
                                         uint32_t b0, uint32_t b1) {
    asm volatile("mma.sync.aligned.m16n8k16.row.col.f32.bf16.bf16.f32 "
                 "{%0,%1,%2,%3},{%4,%5,%6,%7},{%8,%9},{%0,%1,%2,%3};"
                 : "+f"(c[0]), "+f"(c[1]), "+f"(c[2]), "+f"(c[3])
                 : "r"(a[0]), "r"(a[1]), "r"(a[2]), "r"(a[3]), "r"(b0), "r"(b1));
}
__device__ __forceinline__ uint32_t pack_bf16x2(float x, float y) {
    __nv_bfloat16 hx = __float2bfloat16(x), hy = __float2bfloat16(y);
    return (uint32_t)__bfloat16_as_ushort(hx) | ((uint32_t)__bfloat16_as_ushort(hy) << 16);
}
__device__ __forceinline__ void cp_async16(uint32_t saddr, const void* g) {
    asm volatile("cp.async.ca.shared.global [%0], [%1], 16;"
                 :: "r"(saddr), "l"(g) : "memory");
}
#define CP_COMMIT() asm volatile("cp.async.commit_group;" ::: "memory")
#define CP_WAIT0()  asm volatile("cp.async.wait_group 0;" ::: "memory")

// smem layout
#define SM_AHI 0
#define SM_ALO (SM_AHI + 64 * PITCH_B)        // 17408
#define SM_W0H (SM_ALO + 64 * PITCH_B)        // 34816
#define SM_W0L (SM_W0H + 128 * PITCH_B)       // 69632
#define SM_TOT_P (SM_W0L + 128 * PITCH_B)     // 104448 (plain)
#define SM_W1H SM_TOT_P                        // 104448
#define SM_W1L (SM_W1H + 128 * PITCH_B)       // 139264
#define SM_TOT_F (SM_W1L + 128 * PITCH_B)     // 174080 (fused)

// ---- per-tile building blocks (macros; operate on locals in scope) --------
#define LOAD_A_REGS(v, Aptr, tile)                                             \
    {                                                                          \
        int gm = (tile) * 64 + (tid >> 2);                                     \
        if ((tile) < ntiles && gm < M) {                                       \
            const float4* ap = reinterpret_cast<const float4*>(Aptr)           \
                               + (size_t)gm * 32 + (tid & 3) * 8;              \
            _Pragma("unroll")                                                  \
            for (int q = 0; q < 8; q++) {                                      \
                float4 f = __ldg(ap + q);                                      \
                v[4 * q] = f.x; v[4 * q + 1] = f.y;                            \
                v[4 * q + 2] = f.z; v[4 * q + 3] = f.w;                        \
            }                                                                  \
        } else {                                                               \
            _Pragma("unroll")                                                  \
            for (int q = 0; q < 32; q++) v[q] = 0.f;                           \
        }                                                                      \
    }

#define STORE_CONVERT(v)                                                       \
    {                                                                          \
        uint32_t hp[16], lp[16];                                               \
        _Pragma("unroll")                                                      \
        for (int q = 0; q < 16; q++) {                                         \
            float x = v[2 * q], y = v[2 * q + 1];                              \
            uint32_t h = pack_bf16x2(x, y);                                    \
            float hx = __bfloat162float(__ushort_as_bfloat16((unsigned short)(h & 0xFFFF))); \
            float hy = __bfloat162float(__ushort_as_bfloat16((unsigned short)(h >> 16)));    \
            hp[q] = h;                                                         \
            lp[q] = pack_bf16x2(x - hx, y - hy);                               \
        }                                                                      \
        char* dst_h = smem + SM_AHI + (tid >> 2) * PITCH_B + (tid & 3) * 64;   \
        char* dst_l = smem + SM_ALO + (tid >> 2) * PITCH_B + (tid & 3) * 64;   \
        _Pragma("unroll")                                                      \
        for (int q = 0; q < 4; q++) {                                          \
            *reinterpret_cast<uint4*>(dst_h + 16 * q) =                        \
                make_uint4(hp[4 * q], hp[4 * q + 1], hp[4 * q + 2], hp[4 * q + 3]); \
            *reinterpret_cast<uint4*>(dst_l + 16 * q) =                        \
                make_uint4(lp[4 * q], lp[4 * q + 1], lp[4 * q + 2], lp[4 * q + 3]); \
        }                                                                      \
    }

#define ZERO_C()                                                               \
    _Pragma("unroll")                                                          \
    for (int mf = 0; mf < 2; mf++)                                             \
        _Pragma("unroll")                                                      \
        for (int nt = 0; nt < 4; nt++)                                         \
            _Pragma("unroll")                                                  \
            for (int i = 0; i < 4; i++) c[mf][nt][i] = 0.f;

#define MAINLOOP(WHB, WLB)                                                     \
    _Pragma("unroll")                                                          \
    for (int kt = 0; kt < 8; kt++) {                                           \
        const uint32_t kb = kt * 32;                                           \
        uint32_t ah[2][4], al[2][4];                                           \
        ldm_x4(ah[0], sb + SM_AHI + aoff + kb);                                \
        ldm_x4(ah[1], sb + SM_AHI + aoff + 16 * PITCH_B + kb);                 \
        ldm_x4(al[0], sb + SM_ALO + aoff + kb);                                \
        ldm_x4(al[1], sb + SM_ALO + aoff + 16 * PITCH_B + kb);                 \
        uint32_t bh[8], bl[8];                                                 \
        ldm_x4(&bh[0], sb + (WHB) + boff + kb);                                \
        ldm_x4(&bh[4], sb + (WHB) + boff + 16 * PITCH_B + kb);                 \
        ldm_x4(&bl[0], sb + (WLB) + boff + kb);                                \
        ldm_x4(&bl[4], sb + (WLB) + boff + 16 * PITCH_B + kb);                 \
        _Pragma("unroll")                                                      \
        for (int nt = 0; nt < 4; nt++) {                                       \
            uint32_t b0h = bh[2 * nt], b1h = bh[2 * nt + 1];                   \
            uint32_t b0l = bl[2 * nt], b1l = bl[2 * nt + 1];                   \
            _Pragma("unroll")                                                  \
            for (int mf = 0; mf < 2; mf++) {                                   \
                mma_bf16(c[mf][nt], ah[mf], b0h, b1h);                         \
                mma_bf16(c[mf][nt], al[mf], b0h, b1h);                         \
                mma_bf16(c[mf][nt], ah[mf], b0l, b1l);                         \
            }                                                                  \
        }                                                                      \
    }

#define STAGE_W(WHB, WLB, whg, wlg)                                            \
    _Pragma("unroll")                                                          \
    for (int i = tid; i < 2176; i += 256) {                                    \
        cp_async16(sb + (WHB) + i * 16, (const char*)(whg) + i * 16);          \
        cp_async16(sb + (WLB) + i * 16, (const char*)(wlg) + i * 16);          \
    }

// ---------------------------------------------------------------------------
// Persistent plain GEMM: Out = relu(A @ W^T + bias). W staged once per CTA.
// ---------------------------------------------------------------------------
__global__ void __launch_bounds__(256) gemm_plain_kernel(
    const float* __restrict__ A0, const float* __restrict__ bias0,
    const __nv_bfloat16* __restrict__ Wh0, const __nv_bfloat16* __restrict__ Wl0,
    int M, float* __restrict__ Out)
{
    extern __shared__ char smem[];
    const uint32_t sb = smem_u32(smem);
    const int tid = threadIdx.x;
    const int lane = tid & 31;
    const int warp = tid >> 5;
    const int wm = warp & 1;
    const int wn = warp >> 1;
    const int ntiles = (M + 63) / 64;

    const int rA = (lane & 7) + ((lane >> 3) & 1) * 8;
    const int kA = ((lane >> 4) & 1) * 8;
    const int rB = (lane & 7) + ((lane >> 4) & 1) * 8;
    const int kB = ((lane >> 3) & 1) * 8;
    const uint32_t aoff = (uint32_t)((wm * 32 + rA) * PITCH_B + kA * 2);
    const uint32_t boff = (uint32_t)((wn * 32 + rB) * PITCH_B + kB * 2);

    STAGE_W(SM_W0H, SM_W0L, Wh0, Wl0);
    CP_COMMIT();

    float v[32];
    LOAD_A_REGS(v, A0, (int)blockIdx.x);
    CP_WAIT0();

    for (int t = blockIdx.x; t < ntiles; t += gridDim.x) {
        __syncthreads();
        STORE_CONVERT(v);
        __syncthreads();
        LOAD_A_REGS(v, A0, t + (int)gridDim.x);   // prefetch next tile

        float c[2][4][4];
        ZERO_C();
        MAINLOOP(SM_W0H, SM_W0L);

        const int m_base = t * 64;
        #pragma unroll
        for (int nt = 0; nt < 4; nt++) {
            int col = wn * 32 + nt * 8 + 2 * (lane & 3);
            float2 b = __ldg(reinterpret_cast<const float2*>(&bias0[col]));
            #pragma unroll
            for (int mf = 0; mf < 2; mf++) {
                int row0 = m_base + wm * 32 + mf * 16 + (lane >> 2);
                float2 o01 = make_float2(fmaxf(c[mf][nt][0] + b.x, 0.f),
                                         fmaxf(c[mf][nt][1] + b.y, 0.f));
                float2 o23 = make_float2(fmaxf(c[mf][nt][2] + b.x, 0.f),
                                         fmaxf(c[mf][nt][3] + b.y, 0.f));
                if (row0 < M)
                    *reinterpret_cast<float2*>(&Out[(size_t)row0 * D + col]) = o01;
                if (row0 + 8 < M)
                    *reinterpret_cast<float2*>(&Out[(size_t)(row0 + 8) * D + col]) = o23;
            }
        }
    }
}

// ---------------------------------------------------------------------------
// Persistent fused GEMM: Out = relu(A0@W0^T + b0) + A1@W1^T + b1.
// Both W pairs resident (174KB smem, 1 CTA/SM).
// ---------------------------------------------------------------------------
__global__ void __launch_bounds__(256) gemm_fused_kernel(
    const float* __restrict__ A0, const float* __restrict__ bias0,
    const __nv_bfloat16* __restrict__ Wh0, const __nv_bfloat16* __restrict__ Wl0,
    const float* __restrict__ A1, const float* __restrict__ bias1,
    const __nv_bfloat16* __restrict__ Wh1, const __nv_bfloat16* __restrict__ Wl1,
    int M, float* __restrict__ Out)
{
    extern __shared__ char smem[];
    const uint32_t sb = smem_u32(smem);
    const int tid = threadIdx.x;
    const int lane = tid & 31;
    const int warp = tid >> 5;
    const int wm = warp & 1;
    const int wn = warp >> 1;
    const int ntiles = (M + 63) / 64;

    const int rA = (lane & 7) + ((lane >> 3) & 1) * 8;
    const int kA = ((lane >> 4) & 1) * 8;
    const int rB = (lane & 7) + ((lane >> 4) & 1) * 8;
    const int kB = ((lane >> 3) & 1) * 8;
    const uint32_t aoff = (uint32_t)((wm * 32 + rA) * PITCH_B + kA * 2);
    const uint32_t boff = (uint32_t)((wn * 32 + rB) * PITCH_B + kB * 2);

    STAGE_W(SM_W0H, SM_W0L, Wh0, Wl0);
    STAGE_W(SM_W1H, SM_W1L, Wh1, Wl1);
    CP_COMMIT();

    float v0[32], v1[32];
    LOAD_A_REGS(v0, A0, (int)blockIdx.x);
    CP_WAIT0();

    for (int t = blockIdx.x; t < ntiles; t += gridDim.x) {
        __syncthreads();
        STORE_CONVERT(v0);
        __syncthreads();
        LOAD_A_REGS(v1, A1, t);             // prefetch phase-1 A under mainloop0

        float c[2][4][4];
        ZERO_C();
        MAINLOOP(SM_W0H, SM_W0L);

        // mid-fusion: relu(C + bias0)
        #pragma unroll
        for (int nt = 0; nt < 4; nt++) {
            int col = wn * 32 + nt * 8 + 2 * (lane & 3);
            float2 b = __ldg(reinterpret_cast<const float2*>(&bias0[col]));
            #pragma unroll
            for (int mf = 0; mf < 2; mf++) {
                c[mf][nt][0] = fmaxf(c[mf][nt][0] + b.x, 0.f);
                c[mf][nt][1] = fmaxf(c[mf][nt][1] + b.y, 0.f);
                c[mf][nt][2] = fmaxf(c[mf][nt][2] + b.x, 0.f);
                c[mf][nt][3] = fmaxf(c[mf][nt][3] + b.y, 0.f);
            }
        }

        __syncthreads();
        STORE_CONVERT(v1);
        __syncthreads();
        LOAD_A_REGS(v0, A0, t + (int)gridDim.x);  // prefetch next tile under mainloop1

        MAINLOOP(SM_W1H, SM_W1L);

        const int m_base = t * 64;
        #pragma unroll
        for (int nt = 0; nt < 4; nt++) {
            int col = wn * 32 + nt * 8 + 2 * (lane & 3);
            float2 b = __ldg(reinterpret_cast<const float2*>(&bias1[col]));
            #pragma unroll
            for (int mf = 0; mf < 2; mf++) {
                int row0 = m_base + wm * 32 + mf * 16 + (lane >> 2);
                float2 o01 = make_float2(c[mf][nt][0] + b.x, c[mf][nt][1] + b.y);
                float2 o23 = make_float2(c[mf][nt][2] + b.x, c[mf][nt][3] + b.y);
                if (row0 < M)
                    *reinterpret_cast<float2*>(&Out[(size_t)row0 * D + col]) = o01;
                if (row0 + 8 < M)
                    *reinterpret_cast<float2*>(&Out[(size_t)(row0 + 8) * D + col]) = o23;
            }
        }
    }
}

extern "C" void kernel_launch(void* const* d_in, const int* in_sizes, int n_in,
                              void* d_out, int out_size) {
    (void)in_sizes; (void)n_in; (void)out_size;

    const float* vfeat = (const float*)d_in[0];
    const float* efeat = (const float*)d_in[1];
    const float* v_reg_weight = (const float*)d_in[2];
    const float* v_reg_sum    = (const float*)d_in[3];
    const float* e_reg_weight = (const float*)d_in[4];
    const float* e_reg_sum    = (const float*)d_in[5];
    const float* W_ve = (const float*)d_in[6];
    const float* b_ve = (const float*)d_in[7];
    const float* W_ev = (const float*)d_in[8];
    const float* b_ev = (const float*)d_in[9];
    const float* W_ef = (const float*)d_in[10];
    const float* b_ef = (const float*)d_in[11];
    const int* node_idx = (const int*)d_in[12];
    const int* edge_idx = (const int*)d_in[13];

    float* out = (float*)d_out;
    float* vfeat_out = out;
    float* efeat_out = out + (size_t)N_NODES * D;

    float *norm_v_ptr, *norm_e_ptr;
    __nv_bfloat16 *wh_ptr, *wl_ptr;
    int *off_e_ptr, *off_v_ptr, *srt_e_ptr, *srt_v_ptr;
    cudaGetSymbolAddress((void**)&norm_v_ptr, g_norm_v);
    cudaGetSymbolAddress((void**)&norm_e_ptr, g_norm_e);
    cudaGetSymbolAddress((void**)&wh_ptr, g_Wh);
    cudaGetSymbolAddress((void**)&wl_ptr, g_Wl);
    cudaGetSymbolAddress((void**)&off_e_ptr, g_off_e);
    cudaGetSymbolAddress((void**)&off_v_ptr, g_off_v);
    cudaGetSymbolAddress((void**)&srt_e_ptr, g_srt_e);
    cudaGetSymbolAddress((void**)&srt_v_ptr, g_srt_v);

    cudaFuncSetAttribute(gemm_fused_kernel,
                         cudaFuncAttributeMaxDynamicSharedMemorySize, SM_TOT_F);
    cudaFuncSetAttribute(gemm_plain_kernel,
                         cudaFuncAttributeMaxDynamicSharedMemorySize, SM_TOT_P);

    const size_t WSZ = (size_t)D * W_ROW_U16;

    // --- CSR build + weight split (4 launches) ---
    hist_wsplit_kernel<<<HIST_BLOCKS + WSPLIT_BLOCKS, 256>>>(
        node_idx, edge_idx, W_ve, W_ef, W_ev);
    scan_phaseA2<<<NB_E + NB_V, 512>>>();
    scan_phaseC3<<<(N_HEDGES + N_NODES + 255) / 256, 256>>>();
    fill_kernel<<<(N_INC + 255) / 256, 256>>>(node_idx, edge_idx);

    // --- g1: gather nodes -> edges ---
    gather_kernel<<<(N_HEDGES * 32 + 255) / 256, 256>>>(
        vfeat, v_reg_weight, e_reg_sum, off_e_ptr, srt_e_ptr, N_HEDGES, norm_v_ptr);

    // efeat_out = relu(norm_v @ W_ve^T + b_ve) + efeat @ W_ef^T + b_ef
    gemm_fused_kernel<<<NCTA_FUSED, 256, SM_TOT_F>>>(
        norm_v_ptr, b_ve, wh_ptr + 0 * WSZ, wl_ptr + 0 * WSZ,
        efeat, b_ef, wh_ptr + 1 * WSZ, wl_ptr + 1 * WSZ,
        N_HEDGES, efeat_out);

    // --- g2: gather edges -> nodes ---
    gather_kernel<<<(N_NODES * 32 + 255) / 256, 256>>>(
        efeat_out, e_reg_weight, v_reg_sum, off_v_ptr, srt_v_ptr, N_NODES, norm_e_ptr);

    // vfeat_out = relu(norm_e @ W_ev^T + b_ev)
    gemm_plain_kernel<<<NCTA_PLAIN, 256, SM_TOT_P>>>(
        norm_e_ptr, b_ev, wh_ptr + 2 * WSZ, wl_ptr + 2 * WSZ,
        N_NODES, vfeat_out);
}

// round 9
// speedup vs baseline: 2.3957x; 1.0219x over previous
#include <cuda_runtime.h>
#include <cuda_bf16.h>
#include <cstdint>

#define N_NODES 100000
#define N_HEDGES 40000
#define N_INC 600000
#define D 128

#define PITCH_B 272
#define W_ROW_U16 136

#define NB_E ((N_HEDGES + 2047) / 2048)   // 20
#define NB_V ((N_NODES + 2047) / 2048)    // 49
#define HIST_BLOCKS ((N_INC + 255) / 256) // 2344
#define WSPLIT_BLOCKS ((3 * D * D + 255) / 256) // 192
#define FINAL_BLOCKS ((N_HEDGES + N_NODES + 255) / 256) // 547

#define NSM 148
#define NCTA_PLAIN (2 * NSM)   // 296
#define NCTA_FUSED NSM         // 148

// ---------------------------------------------------------------------------
// Scratch (allocation-free __device__ globals; zero-initialized at load).
// ---------------------------------------------------------------------------
static __device__ float g_norm_v[(size_t)N_HEDGES * D];
static __device__ float g_norm_e[(size_t)N_NODES * D];
static __device__ __nv_bfloat16 g_Wh[3][D * W_ROW_U16];
static __device__ __nv_bfloat16 g_Wl[3][D * W_ROW_U16];

// CSR scratch. INVARIANT: g_cnt_* start at 0 (static zero-init); hist counts
// them up, finalize_fill resets them to 0 for the next call.
static __device__ int g_cnt_e[N_HEDGES];
static __device__ int g_cnt_v[N_NODES];
static __device__ int g_offl_e[N_HEDGES];      // block-local exclusive offsets
static __device__ int g_offl_v[N_NODES];
static __device__ int g_offF_e[N_HEDGES + 1];  // final offsets (for gather)
static __device__ int g_offF_v[N_NODES + 1];
static __device__ int g_bsum_e[NB_E];
static __device__ int g_bsum_v[NB_V];
static __device__ int g_pos_e[N_INC];          // within-segment positions
static __device__ int g_pos_v[N_INC];
static __device__ int g_srt_e[N_INC];          // node ids grouped by hyperedge
static __device__ int g_srt_v[N_INC];          // edge ids grouped by node

// ---------------------------------------------------------------------------
// Fused histogram (+position capture) + weight-split (disjoint block ranges).
// ---------------------------------------------------------------------------
__global__ void hist_wsplit_kernel(const int* __restrict__ node_idx,
                                   const int* __restrict__ edge_idx,
                                   const float* __restrict__ W0,
                                   const float* __restrict__ W1,
                                   const float* __restrict__ W2) {
    int b = blockIdx.x;
    if (b < HIST_BLOCKS) {
        int i = b * 256 + threadIdx.x;
        if (i < N_INC) {
            int e = __ldg(&edge_idx[i]);
            int v = __ldg(&node_idx[i]);
            g_pos_e[i] = atomicAdd(&g_cnt_e[e], 1);
            g_pos_v[i] = atomicAdd(&g_cnt_v[v], 1);
        }
    } else {
        int i = (b - HIST_BLOCKS) * 256 + threadIdx.x;
        if (i < 3 * D * D) {
            int w = i >> 14;
            int j = i & (D * D - 1);
            const float* W = (w == 0) ? W0 : (w == 1) ? W1 : W2;
            int n = j >> 7, k = j & 127;
            float x = W[j];
            __nv_bfloat16 hi = __float2bfloat16(x);
            __nv_bfloat16 lo = __float2bfloat16(x - __bfloat162float(hi));
            g_Wh[w][n * W_ROW_U16 + k] = hi;
            g_Wl[w][n * W_ROW_U16 + k] = lo;
        }
    }
}

// ---------------------------------------------------------------------------
// Scan phase A: per-2048-block exclusive scan of counts, totals to bsum.
// ---------------------------------------------------------------------------
__global__ void scan_phaseA2() {
    __shared__ int sm[512];
    int b = blockIdx.x;
    const int* cnt; int* off; int* bsum; int n; int lb;
    if (b < NB_E) { cnt = g_cnt_e; off = g_offl_e; bsum = g_bsum_e; n = N_HEDGES; lb = b; }
    else          { cnt = g_cnt_v; off = g_offl_v; bsum = g_bsum_v; n = N_NODES;  lb = b - NB_E; }

    int t = threadIdx.x;
    int base = lb * 2048 + t * 4;
    int v[4], s = 0;
    #pragma unroll
    for (int q = 0; q < 4; q++) {
        v[q] = (base + q < n) ? cnt[base + q] : 0;
        s += v[q];
    }
    sm[t] = s;
    __syncthreads();
    #pragma unroll
    for (int d = 1; d < 512; d <<= 1) {
        int x = (t >= d) ? sm[t - d] : 0;
        __syncthreads();
        sm[t] += x;
        __syncthreads();
    }
    int run = sm[t] - s;
    #pragma unroll
    for (int q = 0; q < 4; q++) {
        if (base + q < n) off[base + q] = run;
        run += v[q];
    }
    if (t == 511) bsum[lb] = sm[511];
}

// ---------------------------------------------------------------------------
// Fused finalize + fill (disjoint block ranges; both depend only on scanA):
//  - finalize part: g_offF = g_offl + block-base; reset g_cnt to 0.
//  - fill part: atomic-free scatter using precomputed positions.
// Every block redoes the tiny NB_E/NB_V base scans in smem (trivial cost).
// ---------------------------------------------------------------------------
__global__ void finalize_fill_kernel(const int* __restrict__ node_idx,
                                     const int* __restrict__ edge_idx) {
    __shared__ int pe[NB_E], pv[NB_V];
    int t = threadIdx.x;
    if (t < NB_E) pe[t] = g_bsum_e[t];
    else if (t < NB_E + NB_V) pv[t - NB_E] = g_bsum_v[t - NB_E];
    __syncthreads();
    if (t == 0) {
        int run = 0;
        #pragma unroll
        for (int i = 0; i < NB_E; i++) { int x = pe[i]; pe[i] = run; run += x; }
    } else if (t == 32) {
        int run = 0;
        #pragma unroll
        for (int i = 0; i < NB_V; i++) { int x = pv[i]; pv[i] = run; run += x; }
    }
    __syncthreads();

    int b = blockIdx.x;
    if (b < FINAL_BLOCKS) {
        int i = b * 256 + t;
        if (i < N_HEDGES) {
            g_offF_e[i] = g_offl_e[i] + pe[i >> 11];
            g_cnt_e[i] = 0;
        }
        int j = i - N_HEDGES;
        if (j >= 0 && j < N_NODES) {
            g_offF_v[j] = g_offl_v[j] + pv[j >> 11];
            g_cnt_v[j] = 0;
        }
        if (i == 0) { g_offF_e[N_HEDGES] = N_INC; g_offF_v[N_NODES] = N_INC; }
    } else {
        int i = (b - FINAL_BLOCKS) * 256 + t;
        if (i < N_INC) {
            int e = __ldg(&edge_idx[i]);
            int v = __ldg(&node_idx[i]);
            int de = __ldg(&g_offl_e[e]) + pe[e >> 11] + __ldg(&g_pos_e[i]);
            int dv = __ldg(&g_offl_v[v]) + pv[v >> 11] + __ldg(&g_pos_v[i]);
            g_srt_e[de] = v;
            g_srt_v[dv] = e;
        }
    }
}

// ---------------------------------------------------------------------------
// Gather-reduce: out[d] = (sum_{s in seg(d)} src_w[s] * feat[s]) / dst_sum[d]
// ---------------------------------------------------------------------------
__global__ void __launch_bounds__(256) gather_kernel(
    const float* __restrict__ feat, const float* __restrict__ src_w,
    const float* __restrict__ dst_sum, const int* __restrict__ off,
    const int* __restrict__ srt, int n_dst, float* __restrict__ out)
{
    int d = (blockIdx.x * blockDim.x + threadIdx.x) >> 5;
    if (d >= n_dst) return;
    int lane = threadIdx.x & 31;
    int jb = __ldg(&off[d]);
    int je = __ldg(&off[d + 1]);

    float4 acc = make_float4(0.f, 0.f, 0.f, 0.f);
    const float4* f4 = reinterpret_cast<const float4*>(feat);

    int j = jb;
    for (; j + 2 <= je; j += 2) {
        int s0 = __ldg(&srt[j]);
        int s1 = __ldg(&srt[j + 1]);
        float w0 = __ldg(&src_w[s0]);
        float w1 = __ldg(&src_w[s1]);
        float4 a = __ldg(f4 + (size_t)s0 * 32 + lane);
        float4 b = __ldg(f4 + (size_t)s1 * 32 + lane);
        acc.x += w0 * a.x + w1 * b.x;
        acc.y += w0 * a.y + w1 * b.y;
        acc.z += w0 * a.z + w1 * b.z;
        acc.w += w0 * a.w + w1 * b.w;
    }
    if (j < je) {
        int s0 = __ldg(&srt[j]);
        float w0 = __ldg(&src_w[s0]);
        float4 a = __ldg(f4 + (size_t)s0 * 32 + lane);
        acc.x += w0 * a.x; acc.y += w0 * a.y;
        acc.z += w0 * a.z; acc.w += w0 * a.w;
    }

    float rinv = 1.0f / __ldg(&dst_sum[d]);
    acc.x *= rinv; acc.y *= rinv; acc.z *= rinv; acc.w *= rinv;
    reinterpret_cast<float4*>(out)[(size_t)d * 32 + lane] = acc;
}

// ---------------------------------------------------------------------------
// PTX helpers
// ---------------------------------------------------------------------------
__device__ __forceinline__ uint32_t smem_u32(const void* p) {
    uint32_t a;
    asm("{ .reg .u64 t; cvta.to.shared.u64 t, %1; cvt.u32.u64 %0, t; }"
        : "=r"(a) : "l"(p));
    return a;
}
__device__ __forceinline__ void ldm_x4(uint32_t* r, uint32_t addr) {
    asm volatile("ldmatrix.sync.aligned.m8n8.x4.shared.b16 {%0,%1,%2,%3}, [%4];"
                 : "=r"(r[0]), "=r"(r[1]), "=r"(r[2]), "=r"(r[3]) : "r"(addr));
}
__device__ __forceinline__ void mma_bf16(float* c, const uint32_t* a,
                                         uint32_t b0, uint32_t b1) {
    asm volatile("mma.sync.aligned.m16n8k16.row.col.f32.bf16.bf16.f32 "
                 "{%0,%1,%2,%3},{%4,%5,%6,%7},{%8,%9},{%0,%1,%2,%3};"
                 : "+f"(c[0]), "+f"(c[1]), "+f"(c[2]), "+f"(c[3])
                 : "r"(a[0]), "r"(a[1]), "r"(a[2]), "r"(a[3]), "r"(b0), "r"(b1));
}
__device__ __forceinline__ uint32_t pack_bf16x2(float x, float y) {
    __nv_bfloat16 hx = __float2bfloat16(x), hy = __float2bfloat16(y);
    return (uint32_t)__bfloat16_as_ushort(hx) | ((uint32_t)__bfloat16_as_ushort(hy) << 16);
}
__device__ __forceinline__ void cp_async16(uint32_t saddr, const void* g) {
    asm volatile("cp.async.ca.shared.global [%0], [%1], 16;"
                 :: "r"(saddr), "l"(g) : "memory");
}
#define CP_COMMIT() asm volatile("cp.async.commit_group;" ::: "memory")
#define CP_WAIT0()  asm volatile("cp.async.wait_group 0;" ::: "memory")

// smem layout
#define SM_AHI 0
#define SM_ALO (SM_AHI + 64 * PITCH_B)        // 17408
#define SM_W0H (SM_ALO + 64 * PITCH_B)        // 34816
#define SM_W0L (SM_W0H + 128 * PITCH_B)       // 69632
#define SM_TOT_P (SM_W0L + 128 * PITCH_B)     // 104448 (plain)
#define SM_W1H SM_TOT_P                        // 104448
#define SM_W1L (SM_W1H + 128 * PITCH_B)       // 139264
#define SM_TOT_F (SM_W1L + 128 * PITCH_B)     // 174080 (fused)

// ---- per-tile building blocks (macros; operate on locals in scope) --------
#define LOAD_A_REGS(v, Aptr, tile)                                             \
    {                                                                          \
        int gm = (tile) * 64 + (tid >> 2);                                     \
        if ((tile) < ntiles && gm < M) {                                       \
            const float4* ap = reinterpret_cast<const float4*>(Aptr)           \
                               + (size_t)gm * 32 + (tid & 3) * 8;              \
            _Pragma("unroll")                                                  \
            for (int q = 0; q < 8; q++) {                                      \
                float4 f = __ldg(ap + q);                                      \
                v[4 * q] = f.x; v[4 * q + 1] = f.y;                            \
                v[4 * q + 2] = f.z; v[4 * q + 3] = f.w;                        \
            }                                                                  \
        } else {                                                               \
            _Pragma("unroll")                                                  \
            for (int q = 0; q < 32; q++) v[q] = 0.f;                           \
        }                                                                      \
    }

#define STORE_CONVERT(v)                                                       \
    {                                                                          \
        uint32_t hp[16], lp[16];                                               \
        _Pragma("unroll")                                                      \
        for (int q = 0; q < 16; q++) {                                         \
            float x = v[2 * q], y = v[2 * q + 1];                              \
            uint32_t h = pack_bf16x2(x, y);                                    \
            float hx = __bfloat162float(__ushort_as_bfloat16((unsigned short)(h & 0xFFFF))); \
            float hy = __bfloat162float(__ushort_as_bfloat16((unsigned short)(h >> 16)));    \
            hp[q] = h;                                                         \
            lp[q] = pack_bf16x2(x - hx, y - hy);                               \
        }                                                                      \
        char* dst_h = smem + SM_AHI + (tid >> 2) * PITCH_B + (tid & 3) * 64;   \
        char* dst_l = smem + SM_ALO + (tid >> 2) * PITCH_B + (tid & 3) * 64;   \
        _Pragma("unroll")                                                      \
        for (int q = 0; q < 4; q++) {                                          \
            *reinterpret_cast<uint4*>(dst_h + 16 * q) =                        \
                make_uint4(hp[4 * q], hp[4 * q + 1], hp[4 * q + 2], hp[4 * q + 3]); \
            *reinterpret_cast<uint4*>(dst_l + 16 * q) =                        \
                make_uint4(lp[4 * q], lp[4 * q + 1], lp[4 * q + 2], lp[4 * q + 3]); \
        }                                                                      \
    }

#define ZERO_C()                                                               \
    _Pragma("unroll")                                                          \
    for (int mf = 0; mf < 2; mf++)                                             \
        _Pragma("unroll")                                                      \
        for (int nt = 0; nt < 4; nt++)                                         \
            _Pragma("unroll")                                                  \
            for (int i = 0; i < 4; i++) c[mf][nt][i] = 0.f;

#define MAINLOOP(WHB, WLB)                                                     \
    _Pragma("unroll")                                                          \
    for (int kt = 0; kt < 8; kt++) {                                           \
        const uint32_t kb = kt * 32;                                           \
        uint32_t ah[2][4], al[2][4];                                           \
        ldm_x4(ah[0], sb + SM_AHI + aoff + kb);                                \
        ldm_x4(ah[1], sb + SM_AHI + aoff + 16 * PITCH_B + kb);                 \
        ldm_x4(al[0], sb + SM_ALO + aoff + kb);                                \
        ldm_x4(al[1], sb + SM_ALO + aoff + 16 * PITCH_B + kb);                 \
        uint32_t bh[8], bl[8];                                                 \
        ldm_x4(&bh[0], sb + (WHB) + boff + kb);                                \
        ldm_x4(&bh[4], sb + (WHB) + boff + 16 * PITCH_B + kb);                 \
        ldm_x4(&bl[0], sb + (WLB) + boff + kb);                                \
        ldm_x4(&bl[4], sb + (WLB) + boff + 16 * PITCH_B + kb);                 \
        _Pragma("unroll")                                                      \
        for (int nt = 0; nt < 4; nt++) {                                       \
            uint32_t b0h = bh[2 * nt], b1h = bh[2 * nt + 1];                   \
            uint32_t b0l = bl[2 * nt], b1l = bl[2 * nt + 1];                   \
            _Pragma("unroll")                                                  \
            for (int mf = 0; mf < 2; mf++) {                                   \
                mma_bf16(c[mf][nt], ah[mf], b0h, b1h);                         \
                mma_bf16(c[mf][nt], al[mf], b0h, b1h);                         \
                mma_bf16(c[mf][nt], ah[mf], b0l, b1l);                         \
            }                                                                  \
        }                                                                      \
    }

#define STAGE_W(WHB, WLB, whg, wlg)                                            \
    _Pragma("unroll")                                                          \
    for (int i = tid; i < 2176; i += 256) {                                    \
        cp_async16(sb + (WHB) + i * 16, (const char*)(whg) + i * 16);          \
        cp_async16(sb + (WLB) + i * 16, (const char*)(wlg) + i * 16);          \
    }

// ---------------------------------------------------------------------------
// Persistent plain GEMM: Out = relu(A @ W^T + bias). W staged once per CTA.
// ---------------------------------------------------------------------------
__global__ void __launch_bounds__(256) gemm_plain_kernel(
    const float* __restrict__ A0, const float* __restrict__ bias0,
    const __nv_bfloat16* __restrict__ Wh0, const __nv_bfloat16* __restrict__ Wl0,
    int M, float* __restrict__ Out)
{
    extern __shared__ char smem[];
    const uint32_t sb = smem_u32(smem);
    const int tid = threadIdx.x;
    const int lane = tid & 31;
    const int warp = tid >> 5;
    const int wm = warp & 1;
    const int wn = warp >> 1;
    const int ntiles = (M + 63) / 64;

    const int rA = (lane & 7) + ((lane >> 3) & 1) * 8;
    const int kA = ((lane >> 4) & 1) * 8;
    const int rB = (lane & 7) + ((lane >> 4) & 1) * 8;
    const int kB = ((lane >> 3) & 1) * 8;
    const uint32_t aoff = (uint32_t)((wm * 32 + rA) * PITCH_B + kA * 2);
    const uint32_t boff = (uint32_t)((wn * 32 + rB) * PITCH_B + kB * 2);

    STAGE_W(SM_W0H, SM_W0L, Wh0, Wl0);
    CP_COMMIT();

    float v[32];
    LOAD_A_REGS(v, A0, (int)blockIdx.x);
    CP_WAIT0();

    for (int t = blockIdx.x; t < ntiles; t += gridDim.x) {
        __syncthreads();
        STORE_CONVERT(v);
        __syncthreads();
        LOAD_A_REGS(v, A0, t + (int)gridDim.x);   // prefetch next tile

        float c[2][4][4];
        ZERO_C();
        MAINLOOP(SM_W0H, SM_W0L);

        const int m_base = t * 64;
        #pragma unroll
        for (int nt = 0; nt < 4; nt++) {
            int col = wn * 32 + nt * 8 + 2 * (lane & 3);
            float2 b = __ldg(reinterpret_cast<const float2*>(&bias0[col]));
            #pragma unroll
            for (int mf = 0; mf < 2; mf++) {
                int row0 = m_base + wm * 32 + mf * 16 + (lane >> 2);
                float2 o01 = make_float2(fmaxf(c[mf][nt][0] + b.x, 0.f),
                                         fmaxf(c[mf][nt][1] + b.y, 0.f));
                float2 o23 = make_float2(fmaxf(c[mf][nt][2] + b.x, 0.f),
                                         fmaxf(c[mf][nt][3] + b.y, 0.f));
                if (row0 < M)
                    *reinterpret_cast<float2*>(&Out[(size_t)row0 * D + col]) = o01;
                if (row0 + 8 < M)
                    *reinterpret_cast<float2*>(&Out[(size_t)(row0 + 8) * D + col]) = o23;
            }
        }
    }
}

// ---------------------------------------------------------------------------
// Persistent fused GEMM: Out = relu(A0@W0^T + b0) + A1@W1^T + b1.
// Both W pairs resident (174KB smem, 1 CTA/SM).
// ---------------------------------------------------------------------------
__global__ void __launch_bounds__(256) gemm_fused_kernel(
    const float* __restrict__ A0, const float* __restrict__ bias0,
    const __nv_bfloat16* __restrict__ Wh0, const __nv_bfloat16* __restrict__ Wl0,
    const float* __restrict__ A1, const float* __restrict__ bias1,
    const __nv_bfloat16* __restrict__ Wh1, const __nv_bfloat16* __restrict__ Wl1,
    int M, float* __restrict__ Out)
{
    extern __shared__ char smem[];
    const uint32_t sb = smem_u32(smem);
    const int tid = threadIdx.x;
    const int lane = tid & 31;
    const int warp = tid >> 5;
    const int wm = warp & 1;
    const int wn = warp >> 1;
    const int ntiles = (M + 63) / 64;

    const int rA = (lane & 7) + ((lane >> 3) & 1) * 8;
    const int kA = ((lane >> 4) & 1) * 8;
    const int rB = (lane & 7) + ((lane >> 4) & 1) * 8;
    const int kB = ((lane >> 3) & 1) * 8;
    const uint32_t aoff = (uint32_t)((wm * 32 + rA) * PITCH_B + kA * 2);
    const uint32_t boff = (uint32_t)((wn * 32 + rB) * PITCH_B + kB * 2);

    STAGE_W(SM_W0H, SM_W0L, Wh0, Wl0);
    STAGE_W(SM_W1H, SM_W1L, Wh1, Wl1);
    CP_COMMIT();

    float v0[32], v1[32];
    LOAD_A_REGS(v0, A0, (int)blockIdx.x);
    CP_WAIT0();

    for (int t = blockIdx.x; t < ntiles; t += gridDim.x) {
        __syncthreads();
        STORE_CONVERT(v0);
        __syncthreads();
        LOAD_A_REGS(v1, A1, t);             // prefetch phase-1 A under mainloop0

        float c[2][4][4];
        ZERO_C();
        MAINLOOP(SM_W0H, SM_W0L);

        // mid-fusion: relu(C + bias0)
        #pragma unroll
        for (int nt = 0; nt < 4; nt++) {
            int col = wn * 32 + nt * 8 + 2 * (lane & 3);
            float2 b = __ldg(reinterpret_cast<const float2*>(&bias0[col]));
            #pragma unroll
            for (int mf = 0; mf < 2; mf++) {
                c[mf][nt][0] = fmaxf(c[mf][nt][0] + b.x, 0.f);
                c[mf][nt][1] = fmaxf(c[mf][nt][1] + b.y, 0.f);
                c[mf][nt][2] = fmaxf(c[mf][nt][2] + b.x, 0.f);
                c[mf][nt][3] = fmaxf(c[mf][nt][3] + b.y, 0.f);
            }
        }

        __syncthreads();
        STORE_CONVERT(v1);
        __syncthreads();
        LOAD_A_REGS(v0, A0, t + (int)gridDim.x);  // prefetch next tile under mainloop1

        MAINLOOP(SM_W1H, SM_W1L);

        const int m_base = t * 64;
        #pragma unroll
        for (int nt = 0; nt < 4; nt++) {
            int col = wn * 32 + nt * 8 + 2 * (lane & 3);
            float2 b = __ldg(reinterpret_cast<const float2*>(&bias1[col]));
            #pragma unroll
            for (int mf = 0; mf < 2; mf++) {
                int row0 = m_base + wm * 32 + mf * 16 + (lane >> 2);
                float2 o01 = make_float2(c[mf][nt][0] + b.x, c[mf][nt][1] + b.y);
                float2 o23 = make_float2(c[mf][nt][2] + b.x, c[mf][nt][3] + b.y);
                if (row0 < M)
                    *reinterpret_cast<float2*>(&Out[(size_t)row0 * D + col]) = o01;
                if (row0 + 8 < M)
                    *reinterpret_cast<float2*>(&Out[(size_t)(row0 + 8) * D + col]) = o23;
            }
        }
    }
}

extern "C" void kernel_launch(void* const* d_in, const int* in_sizes, int n_in,
                              void* d_out, int out_size) {
    (void)in_sizes; (void)n_in; (void)out_size;

    const float* vfeat = (const float*)d_in[0];
    const float* efeat = (const float*)d_in[1];
    const float* v_reg_weight = (const float*)d_in[2];
    const float* v_reg_sum    = (const float*)d_in[3];
    const float* e_reg_weight = (const float*)d_in[4];
    const float* e_reg_sum    = (const float*)d_in[5];
    const float* W_ve = (const float*)d_in[6];
    const float* b_ve = (const float*)d_in[7];
    const float* W_ev = (const float*)d_in[8];
    const float* b_ev = (const float*)d_in[9];
    const float* W_ef = (const float*)d_in[10];
    const float* b_ef = (const float*)d_in[11];
    const int* node_idx = (const int*)d_in[12];
    const int* edge_idx = (const int*)d_in[13];

    float* out = (float*)d_out;
    float* vfeat_out = out;
    float* efeat_out = out + (size_t)N_NODES * D;

    float *norm_v_ptr, *norm_e_ptr;
    __nv_bfloat16 *wh_ptr, *wl_ptr;
    int *offF_e_ptr, *offF_v_ptr, *srt_e_ptr, *srt_v_ptr;
    cudaGetSymbolAddress((void**)&norm_v_ptr, g_norm_v);
    cudaGetSymbolAddress((void**)&norm_e_ptr, g_norm_e);
    cudaGetSymbolAddress((void**)&wh_ptr, g_Wh);
    cudaGetSymbolAddress((void**)&wl_ptr, g_Wl);
    cudaGetSymbolAddress((void**)&offF_e_ptr, g_offF_e);
    cudaGetSymbolAddress((void**)&offF_v_ptr, g_offF_v);
    cudaGetSymbolAddress((void**)&srt_e_ptr, g_srt_e);
    cudaGetSymbolAddress((void**)&srt_v_ptr, g_srt_v);

    cudaFuncSetAttribute(gemm_fused_kernel,
                         cudaFuncAttributeMaxDynamicSharedMemorySize, SM_TOT_F);
    cudaFuncSetAttribute(gemm_plain_kernel,
                         cudaFuncAttributeMaxDynamicSharedMemorySize, SM_TOT_P);

    const size_t WSZ = (size_t)D * W_ROW_U16;

    // --- CSR build + weight split (3 launches) ---
    hist_wsplit_kernel<<<HIST_BLOCKS + WSPLIT_BLOCKS, 256>>>(
        node_idx, edge_idx, W_ve, W_ef, W_ev);
    scan_phaseA2<<<NB_E + NB_V, 512>>>();
    finalize_fill_kernel<<<FINAL_BLOCKS + HIST_BLOCKS, 256>>>(node_idx, edge_idx);

    // --- g1: gather nodes -> edges ---
    gather_kernel<<<(N_HEDGES * 32 + 255) / 256, 256>>>(
        vfeat, v_reg_weight, e_reg_sum, offF_e_ptr, srt_e_ptr, N_HEDGES, norm_v_ptr);

    // efeat_out = relu(norm_v @ W_ve^T + b_ve) + efeat @ W_ef^T + b_ef
    gemm_fused_kernel<<<NCTA_FUSED, 256, SM_TOT_F>>>(
        norm_v_ptr, b_ve, wh_ptr + 0 * WSZ, wl_ptr + 0 * WSZ,
        efeat, b_ef, wh_ptr + 1 * WSZ, wl_ptr + 1 * WSZ,
        N_HEDGES, efeat_out);

    // --- g2: gather edges -> nodes ---
    gather_kernel<<<(N_NODES * 32 + 255) / 256, 256>>>(
        efeat_out, e_reg_weight, v_reg_sum, offF_v_ptr, srt_v_ptr, N_NODES, norm_e_ptr);

    // vfeat_out = relu(norm_e @ W_ev^T + b_ev)
    gemm_plain_kernel<<<NCTA_PLAIN, 256, SM_TOT_P>>>(
        norm_e_ptr, b_ev, wh_ptr + 2 * WSZ, wl_ptr + 2 * WSZ,
        N_NODES, vfeat_out);
}